// round 1
// baseline (speedup 1.0000x reference)
#include <cuda_runtime.h>
#include <cuda_bf16.h>

// Problem dims (fixed)
#define BC   2
#define LC   1024
#define DM   1024
#define DI   2048
#define DS   16
#define DCNV 4
#define DTR  64
#define MROWS (BC*LC)      // 2048
#define NXZ   (2*DI)       // 4096
#define NDBL  96           // DTR + 2*DS

// Scratch (device globals -- no runtime allocation allowed)
__device__ float g_xz [MROWS * NXZ];   // 32 MB
__device__ float g_xc [MROWS * DI];    // 16 MB
__device__ float g_dbl[MROWS * NDBL];  // 768 KB
__device__ float g_dt [MROWS * DI];    // 16 MB (dt_pre, then softplus in place)
__device__ float g_y  [MROWS * DI];    // 16 MB

// ---------------------------------------------------------------------------
// Fast SGEMM: C[M,N] = A[M,K] @ B[K,N], row-major with leading dims.
// Requires: M%128==0, N%128==0, K%8==0, lda%4==0, ldb%4==0, ldc%4==0.
// 128x128 tile, BK=8, 256 threads, 8x8 per thread.
// ---------------------------------------------------------------------------
__global__ __launch_bounds__(256)
void sgemm128(const float* __restrict__ A, const float* __restrict__ B,
              float* __restrict__ C, int M, int N, int K,
              int lda, int ldb, int ldc)
{
    __shared__ float As[8][128];
    __shared__ float Bs[8][128];

    const int tid = threadIdx.x;
    const int bx  = blockIdx.x;   // N/128
    const int by  = blockIdx.y;   // M/128
    const int tx  = tid % 16;
    const int ty  = tid / 16;

    const int arow = tid >> 1;          // 0..127
    const int acol = (tid & 1) * 4;     // 0 or 4
    const int brow = tid >> 5;          // 0..7
    const int bcol = (tid & 31) * 4;    // 0..124

    const float* Ab = A + (size_t)(by * 128) * lda;
    const float* Bb = B + bx * 128;

    float acc[8][8];
#pragma unroll
    for (int i = 0; i < 8; i++)
#pragma unroll
        for (int j = 0; j < 8; j++) acc[i][j] = 0.f;

    for (int k0 = 0; k0 < K; k0 += 8) {
        float4 av = *(const float4*)(Ab + (size_t)arow * lda + k0 + acol);
        float4 bv = *(const float4*)(Bb + (size_t)(k0 + brow) * ldb + bcol);
        __syncthreads();
        As[acol + 0][arow] = av.x;
        As[acol + 1][arow] = av.y;
        As[acol + 2][arow] = av.z;
        As[acol + 3][arow] = av.w;
        *(float4*)(&Bs[brow][bcol]) = bv;
        __syncthreads();
#pragma unroll
        for (int k = 0; k < 8; k++) {
            float ar[8], br[8];
            float4 a0 = *(const float4*)(&As[k][ty * 8]);
            float4 a1 = *(const float4*)(&As[k][ty * 8 + 4]);
            float4 b0 = *(const float4*)(&Bs[k][tx * 8]);
            float4 b1 = *(const float4*)(&Bs[k][tx * 8 + 4]);
            ar[0]=a0.x; ar[1]=a0.y; ar[2]=a0.z; ar[3]=a0.w;
            ar[4]=a1.x; ar[5]=a1.y; ar[6]=a1.z; ar[7]=a1.w;
            br[0]=b0.x; br[1]=b0.y; br[2]=b0.z; br[3]=b0.w;
            br[4]=b1.x; br[5]=b1.y; br[6]=b1.z; br[7]=b1.w;
#pragma unroll
            for (int i = 0; i < 8; i++)
#pragma unroll
                for (int j = 0; j < 8; j++)
                    acc[i][j] += ar[i] * br[j];
        }
    }

#pragma unroll
    for (int i = 0; i < 8; i++) {
        int row = by * 128 + ty * 8 + i;
        float* Cp = C + (size_t)row * ldc + bx * 128 + tx * 8;
        float4 v0 = make_float4(acc[i][0], acc[i][1], acc[i][2], acc[i][3]);
        float4 v1 = make_float4(acc[i][4], acc[i][5], acc[i][6], acc[i][7]);
        *(float4*)(Cp)     = v0;
        *(float4*)(Cp + 4) = v1;
    }
}

// ---------------------------------------------------------------------------
// Guarded SGEMM for skinny N (dbl = xc @ W_x, N=96). 64x64 tile, BK=16.
// ---------------------------------------------------------------------------
__global__ __launch_bounds__(256)
void sgemm_guard(const float* __restrict__ A, const float* __restrict__ B,
                 float* __restrict__ C, int M, int N, int K,
                 int lda, int ldb, int ldc)
{
    __shared__ float As[16][64];
    __shared__ float Bs[16][64];

    const int tid = threadIdx.x;
    const int bm = blockIdx.y * 64;
    const int bn = blockIdx.x * 64;
    const int tx = tid % 16;
    const int ty = tid / 16;

    float acc[4][4];
#pragma unroll
    for (int i = 0; i < 4; i++)
#pragma unroll
        for (int j = 0; j < 4; j++) acc[i][j] = 0.f;

    for (int k0 = 0; k0 < K; k0 += 16) {
        __syncthreads();
#pragma unroll
        for (int i = 0; i < 4; i++) {
            int e = tid + i * 256;
            int r = e >> 4, c = e & 15;
            float v = 0.f;
            if (bm + r < M && k0 + c < K)
                v = A[(size_t)(bm + r) * lda + k0 + c];
            As[c][r] = v;
        }
#pragma unroll
        for (int i = 0; i < 4; i++) {
            int e = tid + i * 256;
            int r = e >> 6, c = e & 63;
            float v = 0.f;
            if (k0 + r < K && bn + c < N)
                v = B[(size_t)(k0 + r) * ldb + bn + c];
            Bs[r][c] = v;
        }
        __syncthreads();
#pragma unroll
        for (int k = 0; k < 16; k++) {
            float ar[4], br[4];
#pragma unroll
            for (int i = 0; i < 4; i++) ar[i] = As[k][ty * 4 + i];
#pragma unroll
            for (int j = 0; j < 4; j++) br[j] = Bs[k][tx * 4 + j];
#pragma unroll
            for (int i = 0; i < 4; i++)
#pragma unroll
                for (int j = 0; j < 4; j++)
                    acc[i][j] += ar[i] * br[j];
        }
    }

#pragma unroll
    for (int i = 0; i < 4; i++) {
        int row = bm + ty * 4 + i;
        if (row >= M) continue;
#pragma unroll
        for (int j = 0; j < 4; j++) {
            int col = bn + tx * 4 + j;
            if (col < N) C[(size_t)row * ldc + col] = acc[i][j];
        }
    }
}

// ---------------------------------------------------------------------------
// Depthwise causal conv (width 4) + bias + SiLU.
// xs = xz[:, :DI];  xc[b,l,d] = silu(sum_j xs[b, l-3+j, d] * w[d,j] + b[d])
// ---------------------------------------------------------------------------
__global__ void conv_silu_kernel(const float* __restrict__ xz,
                                 const float* __restrict__ conv_w,
                                 const float* __restrict__ conv_b,
                                 float* __restrict__ xc)
{
    int idx = blockIdx.x * blockDim.x + threadIdx.x;  // b*L*DI layout
    if (idx >= MROWS * DI) return;
    int d = idx & (DI - 1);
    int l = (idx >> 11) & (LC - 1);
    int b = idx >> 21;

    float acc = conv_b[d];
#pragma unroll
    for (int j = 0; j < DCNV; j++) {
        int ll = l + j - (DCNV - 1);
        if (ll >= 0)
            acc += xz[(size_t)(b * LC + ll) * NXZ + d] * conv_w[d * DCNV + j];
    }
    xc[idx] = acc / (1.f + __expf(-acc));
}

// ---------------------------------------------------------------------------
// In-place softplus: dt = softplus(dt_pre + b_dt[d])
// ---------------------------------------------------------------------------
__global__ void softplus_kernel(float* __restrict__ dt,
                                const float* __restrict__ b_dt)
{
    int idx = blockIdx.x * blockDim.x + threadIdx.x;
    if (idx >= MROWS * DI) return;
    int d = idx & (DI - 1);
    float v = dt[idx] + b_dt[d];
    dt[idx] = (v > 20.f) ? v : log1pf(expf(v));
}

// ---------------------------------------------------------------------------
// Selective scan. 16 lanes per (b,d) channel, one state n per lane.
//   h = exp(dt*A_n)*h + dt*xc*B[b,l,n];  y = sum_n h*C[b,l,n]
// Fused epilogue: y = (y + xc*D) * silu(z)
// ---------------------------------------------------------------------------
__global__ __launch_bounds__(256)
void scan_kernel(const float* __restrict__ dt,   // [M, DI]
                 const float* __restrict__ xc,   // [M, DI]
                 const float* __restrict__ dbl,  // [M, 96]
                 const float* __restrict__ xz,   // [M, 4096] (z = cols DI..)
                 const float* __restrict__ A_log,// [DI, DS]
                 const float* __restrict__ D_par,// [DI]
                 float* __restrict__ y)          // [M, DI]
{
    const int tid = threadIdx.x;
    const int ch  = blockIdx.x * 16 + (tid >> 4);  // 0..BC*DI-1
    const int n   = tid & 15;
    const int b   = ch >> 11;   // / DI
    const int d   = ch & (DI - 1);

    const float An = -expf(A_log[d * DS + n]);
    const float Dv = D_par[d];
    float h = 0.f;

    const int rowbase = b * LC;
    for (int l = 0; l < LC; ++l) {
        const int row = rowbase + l;
        float dtv = __ldg(&dt[(size_t)row * DI + d]);
        float xcv = __ldg(&xc[(size_t)row * DI + d]);
        float Bv  = __ldg(&dbl[(size_t)row * NDBL + DTR + n]);
        float Cv  = __ldg(&dbl[(size_t)row * NDBL + DTR + DS + n]);

        h = __expf(dtv * An) * h + (dtv * xcv) * Bv;

        float yv = h * Cv;
        yv += __shfl_xor_sync(0xffffffffu, yv, 8);
        yv += __shfl_xor_sync(0xffffffffu, yv, 4);
        yv += __shfl_xor_sync(0xffffffffu, yv, 2);
        yv += __shfl_xor_sync(0xffffffffu, yv, 1);

        if (n == 0) {
            float zv  = __ldg(&xz[(size_t)row * NXZ + DI + d]);
            float sil = zv / (1.f + __expf(-zv));
            y[(size_t)row * DI + d] = (yv + xcv * Dv) * sil;
        }
    }
}

// ---------------------------------------------------------------------------
extern "C" void kernel_launch(void* const* d_in, const int* in_sizes, int n_in,
                              void* d_out, int out_size)
{
    const float* x      = (const float*)d_in[0];
    const float* W_in   = (const float*)d_in[1];
    const float* conv_w = (const float*)d_in[2];
    const float* conv_b = (const float*)d_in[3];
    const float* W_x    = (const float*)d_in[4];
    const float* W_dt   = (const float*)d_in[5];
    const float* b_dt   = (const float*)d_in[6];
    const float* A_log  = (const float*)d_in[7];
    const float* D_par  = (const float*)d_in[8];
    const float* W_out  = (const float*)d_in[9];
    float* out = (float*)d_out;

    float *xz, *xc, *dbl, *dtb, *y;
    cudaGetSymbolAddress((void**)&xz,  g_xz);
    cudaGetSymbolAddress((void**)&xc,  g_xc);
    cudaGetSymbolAddress((void**)&dbl, g_dbl);
    cudaGetSymbolAddress((void**)&dtb, g_dt);
    cudaGetSymbolAddress((void**)&y,   g_y);

    // 1) xz = x @ W_in            (2048 x 1024) @ (1024 x 4096)
    sgemm128<<<dim3(NXZ / 128, MROWS / 128), 256>>>(
        x, W_in, xz, MROWS, NXZ, DM, DM, NXZ, NXZ);

    // 2) depthwise conv + SiLU -> xc
    conv_silu_kernel<<<(MROWS * DI) / 256, 256>>>(xz, conv_w, conv_b, xc);

    // 3) dbl = xc @ W_x           (2048 x 2048) @ (2048 x 96)
    sgemm_guard<<<dim3((NDBL + 63) / 64, MROWS / 64), 256>>>(
        xc, W_x, dbl, MROWS, NDBL, DI, DI, NDBL, NDBL);

    // 4) dt_pre = dbl[:, :64] @ W_dt   (2048 x 64) @ (64 x 2048)
    sgemm128<<<dim3(DI / 128, MROWS / 128), 256>>>(
        dbl, W_dt, dtb, MROWS, DI, DTR, NDBL, DI, DI);

    // 5) dt = softplus(dt_pre + b_dt)
    softplus_kernel<<<(MROWS * DI) / 256, 256>>>(dtb, b_dt);

    // 6) selective scan + gated epilogue -> y
    scan_kernel<<<(BC * DI) / 16, 256>>>(dtb, xc, dbl, xz, A_log, D_par, y);

    // 7) out = y @ W_out          (2048 x 2048) @ (2048 x 1024)
    sgemm128<<<dim3(DM / 128, MROWS / 128), 256>>>(
        y, W_out, out, MROWS, DM, DI, DI, DM, DM);
}

// round 2
// speedup vs baseline: 1.9384x; 1.9384x over previous
#include <cuda_runtime.h>
#include <cuda_bf16.h>
#include <cstdint>

// Problem dims (fixed)
#define BC   2
#define LC   1024
#define DM   1024
#define DI   2048
#define DS   16
#define DCNV 4
#define DTR  64
#define MROWS (BC*LC)      // 2048
#define NXZ   (2*DI)       // 4096
#define NDBL  96

// ---------------- scratch (device globals; no runtime allocation) ----------
__device__ float g_xz [MROWS * NXZ];   // 32 MB
__device__ float g_xc [MROWS * DI];    // 16 MB
__device__ float g_dbl[MROWS * NDBL];  // 768 KB
__device__ float g_dt [MROWS * DI];    // 16 MB

__device__ __nv_bfloat16 g_xh  [MROWS * DM],  g_xl  [MROWS * DM];
__device__ __nv_bfloat16 g_Wih [DM * NXZ],    g_Wil [DM * NXZ];
__device__ __nv_bfloat16 g_dbh [MROWS * DTR], g_dbll[MROWS * DTR];
__device__ __nv_bfloat16 g_Wdh [DTR * DI],    g_Wdl [DTR * DI];
__device__ __nv_bfloat16 g_yh  [MROWS * DI],  g_yl  [MROWS * DI];
__device__ __nv_bfloat16 g_Woh [DI * DM],     g_Wol [DI * DM];

// ---------------------------------------------------------------------------
// fp32 -> bf16 hi/lo split
// ---------------------------------------------------------------------------
__global__ void cvt_kernel(const float* __restrict__ src,
                           __nv_bfloat16* __restrict__ hi,
                           __nv_bfloat16* __restrict__ lo, int n)
{
    int i = blockIdx.x * blockDim.x + threadIdx.x;
    if (i >= n) return;
    float v = src[i];
    __nv_bfloat16 h = __float2bfloat16(v);
    hi[i] = h;
    lo[i] = __float2bfloat16(v - __bfloat162float(h));
}

// dbl[:, 0:64] -> compact bf16 hi/lo (lda 96 -> 64)
__global__ void cvt64_kernel(const float* __restrict__ src,
                             __nv_bfloat16* __restrict__ hi,
                             __nv_bfloat16* __restrict__ lo)
{
    int i = blockIdx.x * blockDim.x + threadIdx.x;
    if (i >= MROWS * DTR) return;
    int row = i >> 6, col = i & 63;
    float v = src[(size_t)row * NDBL + col];
    __nv_bfloat16 h = __float2bfloat16(v);
    hi[i] = h;
    lo[i] = __float2bfloat16(v - __bfloat162float(h));
}

// ---------------------------------------------------------------------------
// Tensor-core GEMM, bf16 split-3: C = (Ah+Al)(Bh+Bl) ~= AhBh + AhBl + AlBh
// 128x128 block tile, BK=16, 256 threads (8 warps as 2x4), cp.async 2-stage.
// Requires M%128==0, N%128==0, K%16==0. Optional fused bias+softplus epilogue.
// ---------------------------------------------------------------------------
#define AS_ST 24            // A smem row stride (bf16), 48B: 16B-aligned, conflict-free
#define BS_ST 136           // B smem row stride (bf16), 272B
#define A_PLANE (128*AS_ST) // 3072
#define B_PLANE (16*BS_ST)  // 2176
#define AH_OFF 0
#define AL_OFF A_PLANE
#define BH_OFF (2*A_PLANE)
#define BL_OFF (2*A_PLANE + B_PLANE)
#define STAGE_SZ (2*A_PLANE + 2*B_PLANE)  // 10496 bf16 = 20992 B

__device__ __forceinline__ void cp16(uint32_t dst, const void* src) {
    asm volatile("cp.async.cg.shared.global [%0], [%1], 16;\n" :: "r"(dst), "l"(src));
}
__device__ __forceinline__ void ldsm4(uint32_t* r, uint32_t addr) {
    asm volatile("ldmatrix.sync.aligned.m8n8.x4.shared.b16 {%0,%1,%2,%3}, [%4];"
                 : "=r"(r[0]), "=r"(r[1]), "=r"(r[2]), "=r"(r[3]) : "r"(addr));
}
__device__ __forceinline__ void ldsm4t(uint32_t* r, uint32_t addr) {
    asm volatile("ldmatrix.sync.aligned.m8n8.x4.trans.shared.b16 {%0,%1,%2,%3}, [%4];"
                 : "=r"(r[0]), "=r"(r[1]), "=r"(r[2]), "=r"(r[3]) : "r"(addr));
}
__device__ __forceinline__ void mma_bf16(float* c, const uint32_t* a, const uint32_t* b) {
    asm volatile("mma.sync.aligned.m16n8k16.row.col.f32.bf16.bf16.f32 "
                 "{%0,%1,%2,%3},{%4,%5,%6,%7},{%8,%9},{%0,%1,%2,%3};"
                 : "+f"(c[0]), "+f"(c[1]), "+f"(c[2]), "+f"(c[3])
                 : "r"(a[0]), "r"(a[1]), "r"(a[2]), "r"(a[3]), "r"(b[0]), "r"(b[1]));
}

__global__ __launch_bounds__(256)
void mma_gemm(const __nv_bfloat16* __restrict__ Ah, const __nv_bfloat16* __restrict__ Al,
              const __nv_bfloat16* __restrict__ Bh, const __nv_bfloat16* __restrict__ Bl,
              float* __restrict__ C, int M, int N, int K,
              int lda, int ldb, int ldc,
              const float* __restrict__ bias)   // bias!=nullptr => softplus(acc+bias[col])
{
    __shared__ __align__(16) __nv_bfloat16 smem[2 * STAGE_SZ];

    const int tid  = threadIdx.x;
    const int lane = tid & 31;
    const int wid  = tid >> 5;
    const int wm   = (wid >> 2) * 64;   // warp M offset (0,64)
    const int wn   = (wid & 3) * 32;    // warp N offset (0..96)
    const int bm   = blockIdx.y * 128;
    const int bn   = blockIdx.x * 128;

    // cp.async thread mapping
    const int ar = tid >> 1,  ac = (tid & 1) * 8;   // A: 128 rows x 2 chunks
    const int br = tid >> 4,  bc = (tid & 15) * 8;  // B: 16 rows x 16 chunks

    const uint32_t sbase = (uint32_t)__cvta_generic_to_shared(smem);

    float acc[4][4][4];
#pragma unroll
    for (int i = 0; i < 4; i++)
#pragma unroll
        for (int j = 0; j < 4; j++)
#pragma unroll
            for (int k = 0; k < 4; k++) acc[i][j][k] = 0.f;

    const int KT = K >> 4;

    // ---- prologue: stage 0 ----
    {
        uint32_t sb = sbase;
        cp16(sb + (AH_OFF + ar * AS_ST + ac) * 2, Ah + (size_t)(bm + ar) * lda + ac);
        cp16(sb + (AL_OFF + ar * AS_ST + ac) * 2, Al + (size_t)(bm + ar) * lda + ac);
        cp16(sb + (BH_OFF + br * BS_ST + bc) * 2, Bh + (size_t)br * ldb + bn + bc);
        cp16(sb + (BL_OFF + br * BS_ST + bc) * 2, Bl + (size_t)br * ldb + bn + bc);
        asm volatile("cp.async.commit_group;\n");
    }

    for (int kt = 0; kt < KT; ++kt) {
        if (kt + 1 < KT) {
            int k0 = (kt + 1) << 4;
            uint32_t sb = sbase + ((kt + 1) & 1) * STAGE_SZ * 2;
            cp16(sb + (AH_OFF + ar * AS_ST + ac) * 2, Ah + (size_t)(bm + ar) * lda + k0 + ac);
            cp16(sb + (AL_OFF + ar * AS_ST + ac) * 2, Al + (size_t)(bm + ar) * lda + k0 + ac);
            cp16(sb + (BH_OFF + br * BS_ST + bc) * 2, Bh + (size_t)(k0 + br) * ldb + bn + bc);
            cp16(sb + (BL_OFF + br * BS_ST + bc) * 2, Bl + (size_t)(k0 + br) * ldb + bn + bc);
            asm volatile("cp.async.commit_group;\n");
            asm volatile("cp.async.wait_group 1;\n");
        } else {
            asm volatile("cp.async.wait_group 0;\n");
        }
        __syncthreads();

        uint32_t sb = sbase + (kt & 1) * STAGE_SZ * 2;

        uint32_t ah[4][4], al[4][4], bh[4][2], bl[4][2];
        const int arow = lane & 15;
        const int acol = (lane >> 4) * 8;
#pragma unroll
        for (int i = 0; i < 4; i++) {
            uint32_t off = (uint32_t)((wm + i * 16 + arow) * AS_ST + acol) * 2;
            ldsm4(ah[i], sb + AH_OFF * 2 + off);
            ldsm4(al[i], sb + AL_OFF * 2 + off);
        }
#pragma unroll
        for (int jj = 0; jj < 2; jj++) {
            uint32_t off = (uint32_t)(arow * BS_ST + wn + jj * 16 + acol) * 2;
            uint32_t r[4];
            ldsm4t(r, sb + BH_OFF * 2 + off);
            bh[2 * jj][0] = r[0]; bh[2 * jj][1] = r[1];
            bh[2 * jj + 1][0] = r[2]; bh[2 * jj + 1][1] = r[3];
            ldsm4t(r, sb + BL_OFF * 2 + off);
            bl[2 * jj][0] = r[0]; bl[2 * jj][1] = r[1];
            bl[2 * jj + 1][0] = r[2]; bl[2 * jj + 1][1] = r[3];
        }
#pragma unroll
        for (int i = 0; i < 4; i++)
#pragma unroll
            for (int j = 0; j < 4; j++) {
                mma_bf16(acc[i][j], ah[i], bh[j]);
                mma_bf16(acc[i][j], ah[i], bl[j]);
                mma_bf16(acc[i][j], al[i], bh[j]);
            }
        __syncthreads();
    }

    // ---- epilogue ----
    const bool sp = (bias != nullptr);
#pragma unroll
    for (int i = 0; i < 4; i++) {
        int row0 = bm + wm + i * 16 + (lane >> 2);
#pragma unroll
        for (int j = 0; j < 4; j++) {
            int col = bn + wn + j * 8 + (lane & 3) * 2;
            float v0 = acc[i][j][0], v1 = acc[i][j][1];
            float v2 = acc[i][j][2], v3 = acc[i][j][3];
            if (sp) {
                float b0 = bias[col], b1 = bias[col + 1];
                v0 += b0; v1 += b1; v2 += b0; v3 += b1;
                v0 = (v0 > 20.f) ? v0 : log1pf(__expf(v0));
                v1 = (v1 > 20.f) ? v1 : log1pf(__expf(v1));
                v2 = (v2 > 20.f) ? v2 : log1pf(__expf(v2));
                v3 = (v3 > 20.f) ? v3 : log1pf(__expf(v3));
            }
            *(float2*)(C + (size_t)row0 * ldc + col)       = make_float2(v0, v1);
            *(float2*)(C + (size_t)(row0 + 8) * ldc + col) = make_float2(v2, v3);
        }
    }
}

// ---------------------------------------------------------------------------
// Guarded fp32 SGEMM for the skinny N=96 GEMM (dbl = xc @ W_x).
// ---------------------------------------------------------------------------
__global__ __launch_bounds__(256)
void sgemm_guard(const float* __restrict__ A, const float* __restrict__ B,
                 float* __restrict__ C, int M, int N, int K,
                 int lda, int ldb, int ldc)
{
    __shared__ float As[16][64];
    __shared__ float Bs[16][64];

    const int tid = threadIdx.x;
    const int bm = blockIdx.y * 64;
    const int bn = blockIdx.x * 64;
    const int tx = tid % 16;
    const int ty = tid / 16;

    float acc[4][4];
#pragma unroll
    for (int i = 0; i < 4; i++)
#pragma unroll
        for (int j = 0; j < 4; j++) acc[i][j] = 0.f;

    for (int k0 = 0; k0 < K; k0 += 16) {
        __syncthreads();
#pragma unroll
        for (int i = 0; i < 4; i++) {
            int e = tid + i * 256;
            int r = e >> 4, c = e & 15;
            float v = 0.f;
            if (bm + r < M && k0 + c < K) v = A[(size_t)(bm + r) * lda + k0 + c];
            As[c][r] = v;
        }
#pragma unroll
        for (int i = 0; i < 4; i++) {
            int e = tid + i * 256;
            int r = e >> 6, c = e & 63;
            float v = 0.f;
            if (k0 + r < K && bn + c < N) v = B[(size_t)(k0 + r) * ldb + bn + c];
            Bs[r][c] = v;
        }
        __syncthreads();
#pragma unroll
        for (int k = 0; k < 16; k++) {
            float ar[4], br[4];
#pragma unroll
            for (int i = 0; i < 4; i++) ar[i] = As[k][ty * 4 + i];
#pragma unroll
            for (int j = 0; j < 4; j++) br[j] = Bs[k][tx * 4 + j];
#pragma unroll
            for (int i = 0; i < 4; i++)
#pragma unroll
                for (int j = 0; j < 4; j++) acc[i][j] += ar[i] * br[j];
        }
    }
#pragma unroll
    for (int i = 0; i < 4; i++) {
        int row = bm + ty * 4 + i;
        if (row >= M) continue;
#pragma unroll
        for (int j = 0; j < 4; j++) {
            int col = bn + tx * 4 + j;
            if (col < N) C[(size_t)row * ldc + col] = acc[i][j];
        }
    }
}

// ---------------------------------------------------------------------------
// Depthwise causal conv (width 4) + bias + SiLU.
// ---------------------------------------------------------------------------
__global__ void conv_silu_kernel(const float* __restrict__ xz,
                                 const float* __restrict__ conv_w,
                                 const float* __restrict__ conv_b,
                                 float* __restrict__ xc)
{
    int idx = blockIdx.x * blockDim.x + threadIdx.x;
    if (idx >= MROWS * DI) return;
    int d = idx & (DI - 1);
    int l = (idx >> 11) & (LC - 1);
    int b = idx >> 21;

    float acc = conv_b[d];
#pragma unroll
    for (int j = 0; j < DCNV; j++) {
        int ll = l + j - (DCNV - 1);
        if (ll >= 0)
            acc += xz[(size_t)(b * LC + ll) * NXZ + d] * conv_w[d * DCNV + j];
    }
    xc[idx] = acc / (1.f + __expf(-acc));
}

// ---------------------------------------------------------------------------
// Selective scan, 16 lanes per channel, depth-1 register prefetch.
// Writes y directly as bf16 hi/lo for the final tensor-core GEMM.
// ---------------------------------------------------------------------------
__global__ __launch_bounds__(256)
void scan_kernel(const float* __restrict__ dt,   // [M, DI]
                 const float* __restrict__ xc,   // [M, DI]
                 const float* __restrict__ dbl,  // [M, 96]
                 const float* __restrict__ xz,   // [M, 4096] (z at cols DI..)
                 const float* __restrict__ A_log,// [DI, DS]
                 const float* __restrict__ D_par,// [DI]
                 __nv_bfloat16* __restrict__ yh,
                 __nv_bfloat16* __restrict__ yl)
{
    const int tid = threadIdx.x;
    const int ch  = blockIdx.x * 16 + (tid >> 4);
    const int n   = tid & 15;
    const int b   = ch >> 11;
    const int d   = ch & (DI - 1);

    const float An = -expf(A_log[d * DS + n]);
    const float Dv = D_par[d];
    float h = 0.f;

    const size_t rowbase = (size_t)b * LC;
    const float* pdt = dt  + rowbase * DI + d;
    const float* pxc = xc  + rowbase * DI + d;
    const float* pB  = dbl + rowbase * NDBL + DTR + n;
    const float* pz  = xz  + rowbase * NXZ + DI + d;
    __nv_bfloat16* pyh = yh + rowbase * DI + d;
    __nv_bfloat16* pyl = yl + rowbase * DI + d;

    float dtv = __ldg(pdt);
    float xcv = __ldg(pxc);
    float Bv  = __ldg(pB);
    float Cv  = __ldg(pB + DS);
    float zv  = (n == 0) ? __ldg(pz) : 0.f;

    for (int l = 0; l < LC; ++l) {
        // prefetch next iteration (addresses independent of h)
        int lp = (l + 1 < LC) ? (l + 1) : l;
        float dtn = __ldg(pdt + (size_t)lp * DI);
        float xcn = __ldg(pxc + (size_t)lp * DI);
        float Bn  = __ldg(pB  + (size_t)lp * NDBL);
        float Cn  = __ldg(pB  + (size_t)lp * NDBL + DS);
        float zn  = (n == 0) ? __ldg(pz + (size_t)lp * NXZ) : 0.f;

        h = __expf(dtv * An) * h + (dtv * xcv) * Bv;

        float yv = h * Cv;
        yv += __shfl_xor_sync(0xffffffffu, yv, 8);
        yv += __shfl_xor_sync(0xffffffffu, yv, 4);
        yv += __shfl_xor_sync(0xffffffffu, yv, 2);
        yv += __shfl_xor_sync(0xffffffffu, yv, 1);

        if (n == 0) {
            float sil = zv / (1.f + __expf(-zv));
            float yo  = (yv + xcv * Dv) * sil;
            __nv_bfloat16 hh = __float2bfloat16(yo);
            pyh[(size_t)l * DI] = hh;
            pyl[(size_t)l * DI] = __float2bfloat16(yo - __bfloat162float(hh));
        }
        dtv = dtn; xcv = xcn; Bv = Bn; Cv = Cn; zv = zn;
    }
}

// ---------------------------------------------------------------------------
extern "C" void kernel_launch(void* const* d_in, const int* in_sizes, int n_in,
                              void* d_out, int out_size)
{
    const float* x      = (const float*)d_in[0];
    const float* W_in   = (const float*)d_in[1];
    const float* conv_w = (const float*)d_in[2];
    const float* conv_b = (const float*)d_in[3];
    const float* W_x    = (const float*)d_in[4];
    const float* W_dt   = (const float*)d_in[5];
    const float* b_dt   = (const float*)d_in[6];
    const float* A_log  = (const float*)d_in[7];
    const float* D_par  = (const float*)d_in[8];
    const float* W_out  = (const float*)d_in[9];
    float* out = (float*)d_out;

    float *xz, *xc, *dbl, *dtb;
    __nv_bfloat16 *xh, *xl, *Wih, *Wil, *dbh, *dbll, *Wdh, *Wdl, *yh, *yl, *Woh, *Wol;
    cudaGetSymbolAddress((void**)&xz,  g_xz);
    cudaGetSymbolAddress((void**)&xc,  g_xc);
    cudaGetSymbolAddress((void**)&dbl, g_dbl);
    cudaGetSymbolAddress((void**)&dtb, g_dt);
    cudaGetSymbolAddress((void**)&xh,  g_xh);   cudaGetSymbolAddress((void**)&xl,  g_xl);
    cudaGetSymbolAddress((void**)&Wih, g_Wih);  cudaGetSymbolAddress((void**)&Wil, g_Wil);
    cudaGetSymbolAddress((void**)&dbh, g_dbh);  cudaGetSymbolAddress((void**)&dbll,g_dbll);
    cudaGetSymbolAddress((void**)&Wdh, g_Wdh);  cudaGetSymbolAddress((void**)&Wdl, g_Wdl);
    cudaGetSymbolAddress((void**)&yh,  g_yh);   cudaGetSymbolAddress((void**)&yl,  g_yl);
    cudaGetSymbolAddress((void**)&Woh, g_Woh);  cudaGetSymbolAddress((void**)&Wol, g_Wol);

    // bf16 hi/lo conversions of GEMM inputs
    cvt_kernel<<<(MROWS * DM + 255) / 256, 256>>>(x, xh, xl, MROWS * DM);
    cvt_kernel<<<(DM * NXZ + 255) / 256, 256>>>(W_in, Wih, Wil, DM * NXZ);
    cvt_kernel<<<(DTR * DI + 255) / 256, 256>>>(W_dt, Wdh, Wdl, DTR * DI);
    cvt_kernel<<<(DI * DM + 255) / 256, 256>>>(W_out, Woh, Wol, DI * DM);

    // 1) xz = x @ W_in   (2048 x 1024 x 4096), tensor cores
    mma_gemm<<<dim3(NXZ / 128, MROWS / 128), 256>>>(
        xh, xl, Wih, Wil, xz, MROWS, NXZ, DM, DM, NXZ, NXZ, nullptr);

    // 2) depthwise conv + SiLU
    conv_silu_kernel<<<(MROWS * DI) / 256, 256>>>(xz, conv_w, conv_b, xc);

    // 3) dbl = xc @ W_x  (N=96, fp32 guarded)
    sgemm_guard<<<dim3((NDBL + 63) / 64, MROWS / 64), 256>>>(
        xc, W_x, dbl, MROWS, NDBL, DI, DI, NDBL, NDBL);

    // 4) dbl[:, :64] -> bf16 hi/lo compact
    cvt64_kernel<<<(MROWS * DTR + 255) / 256, 256>>>(dbl, dbh, dbll);

    // 5) dt = softplus(dbl[:,:64] @ W_dt + b_dt)  -- fused epilogue
    mma_gemm<<<dim3(DI / 128, MROWS / 128), 256>>>(
        dbh, dbll, Wdh, Wdl, dtb, MROWS, DI, DTR, DTR, DI, DI, b_dt);

    // 6) selective scan + gated epilogue -> y (bf16 hi/lo)
    scan_kernel<<<(BC * DI) / 16, 256>>>(dtb, xc, dbl, xz, A_log, D_par, yh, yl);

    // 7) out = y @ W_out (2048 x 2048 x 1024), tensor cores
    mma_gemm<<<dim3(DM / 128, MROWS / 128), 256>>>(
        yh, yl, Woh, Wol, out, MROWS, DM, DI, DI, DM, DM, nullptr);
}

// round 3
// speedup vs baseline: 2.1868x; 1.1281x over previous
#include <cuda_runtime.h>
#include <cuda_bf16.h>
#include <cstdint>

// Problem dims (fixed)
#define BC   2
#define LC   1024
#define DM   1024
#define DI   2048
#define DS   16
#define DCNV 4
#define DTR  64
#define MROWS (BC*LC)      // 2048
#define NXZ   (2*DI)       // 4096
#define NDP   128          // padded dbl width

// ---------------- scratch (device globals; no runtime allocation) ----------
__device__ float g_xz  [MROWS * NXZ];       // 32 MB
__device__ float g_xc  [MROWS * DI];        // 16 MB
__device__ float g_dt  [MROWS * DI];        // 16 MB
__device__ float g_dbl [MROWS * NDP];       // 1 MB
__device__ float g_dblp[8 * MROWS * NDP];   // 8 MB (K-split partials)

__device__ __nv_bfloat16 g_xh  [MROWS * DM],  g_xl  [MROWS * DM];
__device__ __nv_bfloat16 g_Wih [DM * NXZ],    g_Wil [DM * NXZ];
__device__ __nv_bfloat16 g_Wxh [DI * NDP],    g_Wxl [DI * NDP];
__device__ __nv_bfloat16 g_xch [MROWS * DI],  g_xcl [MROWS * DI];
__device__ __nv_bfloat16 g_dbh [MROWS * DTR], g_dbll[MROWS * DTR];
__device__ __nv_bfloat16 g_Wdh [DTR * DI],    g_Wdl [DTR * DI];
__device__ __nv_bfloat16 g_yh  [MROWS * DI],  g_yl  [MROWS * DI];
__device__ __nv_bfloat16 g_Woh [DI * DM],     g_Wol [DI * DM];

// ---------------------------------------------------------------------------
// helpers
// ---------------------------------------------------------------------------
__device__ __forceinline__ uint32_t pack_bf2(float a, float b) {
    __nv_bfloat162 h = __floats2bfloat162_rn(a, b);
    return *reinterpret_cast<uint32_t*>(&h);
}

// fp32 -> bf16 hi/lo split, vectorized x4. n must be %4.
__global__ void cvt4_kernel(const float4* __restrict__ src,
                            uint2* __restrict__ hi, uint2* __restrict__ lo, int n4)
{
    int i = blockIdx.x * blockDim.x + threadIdx.x;
    if (i >= n4) return;
    float4 v = src[i];
    float hx = __bfloat162float(__float2bfloat16(v.x));
    float hy = __bfloat162float(__float2bfloat16(v.y));
    float hz = __bfloat162float(__float2bfloat16(v.z));
    float hw = __bfloat162float(__float2bfloat16(v.w));
    uint2 H, L;
    H.x = pack_bf2(v.x, v.y);       H.y = pack_bf2(v.z, v.w);
    L.x = pack_bf2(v.x - hx, v.y - hy); L.y = pack_bf2(v.z - hz, v.w - hw);
    hi[i] = H; lo[i] = L;
}

// W_x (2048 x 96) -> padded bf16 hi/lo (2048 x 128), cols 96.. zero
__global__ void cvt_wx_kernel(const float* __restrict__ W,
                              __nv_bfloat16* __restrict__ hi,
                              __nv_bfloat16* __restrict__ lo)
{
    int i = blockIdx.x * blockDim.x + threadIdx.x;
    if (i >= DI * NDP) return;
    int r = i >> 7, c = i & 127;
    float v = (c < 96) ? W[r * 96 + c] : 0.f;
    __nv_bfloat16 h = __float2bfloat16(v);
    hi[i] = h;
    lo[i] = __float2bfloat16(v - __bfloat162float(h));
}

// sum 8 K-split partial slabs -> dbl, and emit compact bf16 hi/lo of cols 0..63
__global__ void reduce_dbl_kernel(const float* __restrict__ parts,
                                  float* __restrict__ dbl,
                                  __nv_bfloat16* __restrict__ dbh,
                                  __nv_bfloat16* __restrict__ dbll)
{
    int i = blockIdx.x * blockDim.x + threadIdx.x;
    if (i >= MROWS * NDP) return;
    float s = 0.f;
#pragma unroll
    for (int k = 0; k < 8; k++) s += parts[(size_t)k * MROWS * NDP + i];
    dbl[i] = s;
    int c = i & 127;
    if (c < 64) {
        int r = i >> 7;
        __nv_bfloat16 h = __float2bfloat16(s);
        dbh [r * DTR + c] = h;
        dbll[r * DTR + c] = __float2bfloat16(s - __bfloat162float(h));
    }
}

// ---------------------------------------------------------------------------
// Tensor-core GEMM, bf16 split-3, 128x128 tile, BK=16, 3-stage cp.async,
// optional K-split (blockIdx.z) and fused bias+softplus epilogue.
// ---------------------------------------------------------------------------
#define AS_ST 24
#define BS_ST 136
#define A_PLANE (128*AS_ST)
#define B_PLANE (16*BS_ST)
#define AH_OFF 0
#define AL_OFF A_PLANE
#define BH_OFF (2*A_PLANE)
#define BL_OFF (2*A_PLANE + B_PLANE)
#define STAGE_SZ (2*A_PLANE + 2*B_PLANE)        // elems
#define STAGE_B  (STAGE_SZ*2)                   // bytes: 20992
#define SMEM_TOT (3*STAGE_B)                    // 62976

__device__ __forceinline__ void cp16(uint32_t dst, const void* src) {
    asm volatile("cp.async.cg.shared.global [%0], [%1], 16;\n" :: "r"(dst), "l"(src));
}
__device__ __forceinline__ void ldsm4(uint32_t* r, uint32_t addr) {
    asm volatile("ldmatrix.sync.aligned.m8n8.x4.shared.b16 {%0,%1,%2,%3}, [%4];"
                 : "=r"(r[0]), "=r"(r[1]), "=r"(r[2]), "=r"(r[3]) : "r"(addr));
}
__device__ __forceinline__ void ldsm4t(uint32_t* r, uint32_t addr) {
    asm volatile("ldmatrix.sync.aligned.m8n8.x4.trans.shared.b16 {%0,%1,%2,%3}, [%4];"
                 : "=r"(r[0]), "=r"(r[1]), "=r"(r[2]), "=r"(r[3]) : "r"(addr));
}
__device__ __forceinline__ void mma_bf16(float* c, const uint32_t* a, const uint32_t* b) {
    asm volatile("mma.sync.aligned.m16n8k16.row.col.f32.bf16.bf16.f32 "
                 "{%0,%1,%2,%3},{%4,%5,%6,%7},{%8,%9},{%0,%1,%2,%3};"
                 : "+f"(c[0]), "+f"(c[1]), "+f"(c[2]), "+f"(c[3])
                 : "r"(a[0]), "r"(a[1]), "r"(a[2]), "r"(a[3]), "r"(b[0]), "r"(b[1]));
}

__global__ __launch_bounds__(256)
void mma_gemm(const __nv_bfloat16* __restrict__ Ah, const __nv_bfloat16* __restrict__ Al,
              const __nv_bfloat16* __restrict__ Bh, const __nv_bfloat16* __restrict__ Bl,
              float* __restrict__ C, int Kchunk,
              int lda, int ldb, int ldc,
              size_t slabStride,                 // C += blockIdx.z * slabStride
              const float* __restrict__ bias)    // != nullptr => softplus(acc + bias[col])
{
    extern __shared__ __align__(16) char dynsmem[];
    __nv_bfloat16* smem = reinterpret_cast<__nv_bfloat16*>(dynsmem);

    const int tid  = threadIdx.x;
    const int lane = tid & 31;
    const int wid  = tid >> 5;
    const int wm   = (wid >> 2) * 64;
    const int wn   = (wid & 3) * 32;
    const int bm   = blockIdx.y * 128;
    const int bn   = blockIdx.x * 128;
    const int kb   = blockIdx.z * Kchunk;

    C += (size_t)blockIdx.z * slabStride;

    const int ar = tid >> 1,  ac = (tid & 1) * 8;
    const int br = tid >> 4,  bc = (tid & 15) * 8;

    const uint32_t sbase = (uint32_t)__cvta_generic_to_shared(smem);

    float acc[4][4][4];
#pragma unroll
    for (int i = 0; i < 4; i++)
#pragma unroll
        for (int j = 0; j < 4; j++)
#pragma unroll
            for (int k = 0; k < 4; k++) acc[i][j][k] = 0.f;

    const int KT = Kchunk >> 4;

    const __nv_bfloat16* Abh = Ah + (size_t)(bm + ar) * lda + kb + ac;
    const __nv_bfloat16* Abl = Al + (size_t)(bm + ar) * lda + kb + ac;
    const __nv_bfloat16* Bbh = Bh + (size_t)(kb + br) * ldb + bn + bc;
    const __nv_bfloat16* Bbl = Bl + (size_t)(kb + br) * ldb + bn + bc;

#define ISSUE(stage, kt_) {                                                   \
        uint32_t sb = sbase + (stage) * STAGE_B;                              \
        int k0 = (kt_) << 4;                                                  \
        cp16(sb + (AH_OFF + ar * AS_ST + ac) * 2, Abh + k0);                  \
        cp16(sb + (AL_OFF + ar * AS_ST + ac) * 2, Abl + k0);                  \
        cp16(sb + (BH_OFF + br * BS_ST + bc) * 2, Bbh + (size_t)k0 * ldb);    \
        cp16(sb + (BL_OFF + br * BS_ST + bc) * 2, Bbl + (size_t)k0 * ldb);    \
    }

    // prologue: stages 0,1
    ISSUE(0, 0);
    asm volatile("cp.async.commit_group;\n");
    if (KT > 1) ISSUE(1, 1);
    asm volatile("cp.async.commit_group;\n");

    for (int kt = 0; kt < KT; ++kt) {
        asm volatile("cp.async.wait_group 1;\n");
        __syncthreads();

        if (kt + 2 < KT) ISSUE((kt + 2) % 3, kt + 2);
        asm volatile("cp.async.commit_group;\n");

        uint32_t sb = sbase + (kt % 3) * STAGE_B;
        uint32_t ah[4][4], al[4][4], bh[4][2], bl[4][2];
        const int arow = lane & 15;
        const int acol = (lane >> 4) * 8;
#pragma unroll
        for (int i = 0; i < 4; i++) {
            uint32_t off = (uint32_t)((wm + i * 16 + arow) * AS_ST + acol) * 2;
            ldsm4(ah[i], sb + AH_OFF * 2 + off);
            ldsm4(al[i], sb + AL_OFF * 2 + off);
        }
#pragma unroll
        for (int jj = 0; jj < 2; jj++) {
            uint32_t off = (uint32_t)(arow * BS_ST + wn + jj * 16 + acol) * 2;
            uint32_t r[4];
            ldsm4t(r, sb + BH_OFF * 2 + off);
            bh[2 * jj][0] = r[0]; bh[2 * jj][1] = r[1];
            bh[2 * jj + 1][0] = r[2]; bh[2 * jj + 1][1] = r[3];
            ldsm4t(r, sb + BL_OFF * 2 + off);
            bl[2 * jj][0] = r[0]; bl[2 * jj][1] = r[1];
            bl[2 * jj + 1][0] = r[2]; bl[2 * jj + 1][1] = r[3];
        }
#pragma unroll
        for (int i = 0; i < 4; i++)
#pragma unroll
            for (int j = 0; j < 4; j++) {
                mma_bf16(acc[i][j], ah[i], bh[j]);
                mma_bf16(acc[i][j], ah[i], bl[j]);
                mma_bf16(acc[i][j], al[i], bh[j]);
            }
    }
#undef ISSUE

    const bool sp = (bias != nullptr);
#pragma unroll
    for (int i = 0; i < 4; i++) {
        int row0 = bm + wm + i * 16 + (lane >> 2);
#pragma unroll
        for (int j = 0; j < 4; j++) {
            int col = bn + wn + j * 8 + (lane & 3) * 2;
            float v0 = acc[i][j][0], v1 = acc[i][j][1];
            float v2 = acc[i][j][2], v3 = acc[i][j][3];
            if (sp) {
                float b0 = bias[col], b1 = bias[col + 1];
                v0 += b0; v1 += b1; v2 += b0; v3 += b1;
                v0 = (v0 > 20.f) ? v0 : log1pf(__expf(v0));
                v1 = (v1 > 20.f) ? v1 : log1pf(__expf(v1));
                v2 = (v2 > 20.f) ? v2 : log1pf(__expf(v2));
                v3 = (v3 > 20.f) ? v3 : log1pf(__expf(v3));
            }
            *(float2*)(C + (size_t)row0 * ldc + col)       = make_float2(v0, v1);
            *(float2*)(C + (size_t)(row0 + 8) * ldc + col) = make_float2(v2, v3);
        }
    }
}

// ---------------------------------------------------------------------------
// Depthwise causal conv (width 4) + bias + SiLU; emits fp32 + bf16 hi/lo.
// ---------------------------------------------------------------------------
__global__ void conv_silu_kernel(const float* __restrict__ xz,
                                 const float* __restrict__ conv_w,
                                 const float* __restrict__ conv_b,
                                 float* __restrict__ xc,
                                 __nv_bfloat16* __restrict__ xch,
                                 __nv_bfloat16* __restrict__ xcl)
{
    int idx = blockIdx.x * blockDim.x + threadIdx.x;
    if (idx >= MROWS * DI) return;
    int d = idx & (DI - 1);
    int l = (idx >> 11) & (LC - 1);
    int b = idx >> 21;

    float acc = conv_b[d];
#pragma unroll
    for (int j = 0; j < DCNV; j++) {
        int ll = l + j - (DCNV - 1);
        if (ll >= 0)
            acc += xz[(size_t)(b * LC + ll) * NXZ + d] * conv_w[d * DCNV + j];
    }
    float v = acc / (1.f + __expf(-acc));
    xc[idx] = v;
    __nv_bfloat16 h = __float2bfloat16(v);
    xch[idx] = h;
    xcl[idx] = __float2bfloat16(v - __bfloat162float(h));
}

// ---------------------------------------------------------------------------
// Selective scan: 8 lanes/channel, 2 states/lane, depth-1 prefetch.
// ---------------------------------------------------------------------------
__global__ __launch_bounds__(256)
void scan_kernel(const float* __restrict__ dt,   // [M, DI]
                 const float* __restrict__ xc,   // [M, DI]
                 const float* __restrict__ dbl,  // [M, 128] (B at 64.., C at 80..)
                 const float* __restrict__ xz,   // [M, 4096] (z at DI..)
                 const float* __restrict__ A_log,
                 const float* __restrict__ D_par,
                 __nv_bfloat16* __restrict__ yh,
                 __nv_bfloat16* __restrict__ yl)
{
    const int gtid = blockIdx.x * 256 + threadIdx.x;
    const int ch = gtid >> 3;        // 0..4095
    const int nl = gtid & 7;
    const int n0 = nl * 2;
    const int b  = ch >> 11;
    const int d  = ch & (DI - 1);

    const float An0 = -expf(A_log[d * DS + n0]);
    const float An1 = -expf(A_log[d * DS + n0 + 1]);
    const float Dv  = D_par[d];
    float h0 = 0.f, h1 = 0.f;

    const size_t rowbase = (size_t)b * LC;
    const float* pdt = dt  + rowbase * DI + d;
    const float* pxc = xc  + rowbase * DI + d;
    const float* pBC = dbl + rowbase * NDP + 64 + n0;
    const float* pz  = xz  + rowbase * NXZ + DI + d;
    __nv_bfloat16* pyh = yh + rowbase * DI + d;
    __nv_bfloat16* pyl = yl + rowbase * DI + d;

    float  dtv = __ldg(pdt);
    float  xcv = __ldg(pxc);
    float2 Bv  = __ldg((const float2*)pBC);
    float2 Cv  = __ldg((const float2*)(pBC + DS));
    float  zv  = (nl == 0) ? __ldg(pz) : 0.f;

    for (int l = 0; l < LC; ++l) {
        int lp = (l + 1 < LC) ? (l + 1) : l;
        float  dtn = __ldg(pdt + (size_t)lp * DI);
        float  xcn = __ldg(pxc + (size_t)lp * DI);
        float2 Bn  = __ldg((const float2*)(pBC + (size_t)lp * NDP));
        float2 Cn  = __ldg((const float2*)(pBC + (size_t)lp * NDP + DS));
        float  zn  = (nl == 0) ? __ldg(pz + (size_t)lp * NXZ) : 0.f;

        float dx = dtv * xcv;
        h0 = __expf(dtv * An0) * h0 + dx * Bv.x;
        h1 = __expf(dtv * An1) * h1 + dx * Bv.y;

        float yv = h0 * Cv.x + h1 * Cv.y;
        yv += __shfl_xor_sync(0xffffffffu, yv, 4);
        yv += __shfl_xor_sync(0xffffffffu, yv, 2);
        yv += __shfl_xor_sync(0xffffffffu, yv, 1);

        if (nl == 0) {
            float sil = zv / (1.f + __expf(-zv));
            float yo  = (yv + xcv * Dv) * sil;
            __nv_bfloat16 hh = __float2bfloat16(yo);
            pyh[(size_t)l * DI] = hh;
            pyl[(size_t)l * DI] = __float2bfloat16(yo - __bfloat162float(hh));
        }
        dtv = dtn; xcv = xcn; Bv = Bn; Cv = Cn; zv = zn;
    }
}

// ---------------------------------------------------------------------------
extern "C" void kernel_launch(void* const* d_in, const int* in_sizes, int n_in,
                              void* d_out, int out_size)
{
    const float* x      = (const float*)d_in[0];
    const float* W_in   = (const float*)d_in[1];
    const float* conv_w = (const float*)d_in[2];
    const float* conv_b = (const float*)d_in[3];
    const float* W_x    = (const float*)d_in[4];
    const float* W_dt   = (const float*)d_in[5];
    const float* b_dt   = (const float*)d_in[6];
    const float* A_log  = (const float*)d_in[7];
    const float* D_par  = (const float*)d_in[8];
    const float* W_out  = (const float*)d_in[9];
    float* out = (float*)d_out;

    float *xz, *xc, *dtb, *dbl, *dblp;
    __nv_bfloat16 *xh, *xl, *Wih, *Wil, *Wxh, *Wxl, *xch, *xcl,
                  *dbh, *dbll, *Wdh, *Wdl, *yh, *yl, *Woh, *Wol;
    cudaGetSymbolAddress((void**)&xz,   g_xz);
    cudaGetSymbolAddress((void**)&xc,   g_xc);
    cudaGetSymbolAddress((void**)&dtb,  g_dt);
    cudaGetSymbolAddress((void**)&dbl,  g_dbl);
    cudaGetSymbolAddress((void**)&dblp, g_dblp);
    cudaGetSymbolAddress((void**)&xh,   g_xh);   cudaGetSymbolAddress((void**)&xl,   g_xl);
    cudaGetSymbolAddress((void**)&Wih,  g_Wih);  cudaGetSymbolAddress((void**)&Wil,  g_Wil);
    cudaGetSymbolAddress((void**)&Wxh,  g_Wxh);  cudaGetSymbolAddress((void**)&Wxl,  g_Wxl);
    cudaGetSymbolAddress((void**)&xch,  g_xch);  cudaGetSymbolAddress((void**)&xcl,  g_xcl);
    cudaGetSymbolAddress((void**)&dbh,  g_dbh);  cudaGetSymbolAddress((void**)&dbll, g_dbll);
    cudaGetSymbolAddress((void**)&Wdh,  g_Wdh);  cudaGetSymbolAddress((void**)&Wdl,  g_Wdl);
    cudaGetSymbolAddress((void**)&yh,   g_yh);   cudaGetSymbolAddress((void**)&yl,   g_yl);
    cudaGetSymbolAddress((void**)&Woh,  g_Woh);  cudaGetSymbolAddress((void**)&Wol,  g_Wol);

    cudaFuncSetAttribute(mma_gemm, cudaFuncAttributeMaxDynamicSharedMemorySize, SMEM_TOT);

    // conversions (vectorized)
    cvt4_kernel<<<(MROWS * DM / 4 + 255) / 256, 256>>>((const float4*)x, (uint2*)xh, (uint2*)xl, MROWS * DM / 4);
    cvt4_kernel<<<(DM * NXZ / 4 + 255) / 256, 256>>>((const float4*)W_in, (uint2*)Wih, (uint2*)Wil, DM * NXZ / 4);
    cvt4_kernel<<<(DTR * DI / 4 + 255) / 256, 256>>>((const float4*)W_dt, (uint2*)Wdh, (uint2*)Wdl, DTR * DI / 4);
    cvt4_kernel<<<(DI * DM / 4 + 255) / 256, 256>>>((const float4*)W_out, (uint2*)Woh, (uint2*)Wol, DI * DM / 4);
    cvt_wx_kernel<<<(DI * NDP + 255) / 256, 256>>>(W_x, Wxh, Wxl);

    // 1) xz = x @ W_in
    mma_gemm<<<dim3(NXZ / 128, MROWS / 128, 1), 256, SMEM_TOT>>>(
        xh, xl, Wih, Wil, xz, DM, DM, NXZ, NXZ, 0, nullptr);

    // 2) conv + SiLU (+ bf16 split)
    conv_silu_kernel<<<(MROWS * DI) / 256, 256>>>(xz, conv_w, conv_b, xc, xch, xcl);

    // 3) dbl = xc @ W_x_padded, K-split 8
    mma_gemm<<<dim3(1, MROWS / 128, 8), 256, SMEM_TOT>>>(
        xch, xcl, Wxh, Wxl, dblp, DI / 8, DI, NDP, NDP,
        (size_t)MROWS * NDP, nullptr);

    // 4) reduce partials + compact bf16 of dt-rank slice
    reduce_dbl_kernel<<<(MROWS * NDP + 255) / 256, 256>>>(dblp, dbl, dbh, dbll);

    // 5) dt = softplus(dbl[:,:64] @ W_dt + b_dt)
    mma_gemm<<<dim3(DI / 128, MROWS / 128, 1), 256, SMEM_TOT>>>(
        dbh, dbll, Wdh, Wdl, dtb, DTR, DTR, DI, DI, 0, b_dt);

    // 6) selective scan -> y (bf16 hi/lo)
    scan_kernel<<<(BC * DI * 8) / 256, 256>>>(dtb, xc, dbl, xz, A_log, D_par, yh, yl);

    // 7) out = y @ W_out
    mma_gemm<<<dim3(DM / 128, MROWS / 128, 1), 256, SMEM_TOT>>>(
        yh, yl, Woh, Wol, out, DI, DI, DM, DM, 0, nullptr);
}

// round 5
// speedup vs baseline: 2.1977x; 1.0050x over previous
#include <cuda_runtime.h>
#include <cuda_bf16.h>
#include <cstdint>

// Problem dims (fixed)
#define BC   2
#define LC   1024
#define DM   1024
#define DI   2048
#define DS   16
#define DCNV 4
#define DTR  64
#define MROWS (BC*LC)      // 2048
#define NXZ   (2*DI)       // 4096
#define NDP   128          // padded dbl width

// ---------------- scratch (device globals; no runtime allocation) ----------
__device__ float g_xz  [MROWS * NXZ];       // 32 MB
__device__ float g_xc  [MROWS * DI];        // 16 MB
__device__ float g_dt  [MROWS * DI];        // 16 MB
__device__ float g_dbl [MROWS * NDP];       // 1 MB
__device__ float g_dblp[8 * MROWS * NDP];   // 8 MB (K-split partials)

__device__ __nv_bfloat16 g_xh  [MROWS * DM],  g_xl  [MROWS * DM];
__device__ __nv_bfloat16 g_Wih [DM * NXZ],    g_Wil [DM * NXZ];
__device__ __nv_bfloat16 g_Wxh [DI * NDP],    g_Wxl [DI * NDP];
__device__ __nv_bfloat16 g_xch [MROWS * DI],  g_xcl [MROWS * DI];
__device__ __nv_bfloat16 g_dbh [MROWS * DTR], g_dbll[MROWS * DTR];
__device__ __nv_bfloat16 g_Wdh [DTR * DI],    g_Wdl [DTR * DI];
__device__ __nv_bfloat16 g_yh  [MROWS * DI],  g_yl  [MROWS * DI];
__device__ __nv_bfloat16 g_Woh [DI * DM],     g_Wol [DI * DM];

// ---------------------------------------------------------------------------
// helpers
// ---------------------------------------------------------------------------
__device__ __forceinline__ uint32_t pack_bf2(float a, float b) {
    __nv_bfloat162 h = __floats2bfloat162_rn(a, b);
    return *reinterpret_cast<uint32_t*>(&h);
}

// fp32 -> bf16 hi/lo split, vectorized x4. n must be %4.
__global__ void cvt4_kernel(const float4* __restrict__ src,
                            uint2* __restrict__ hi, uint2* __restrict__ lo, int n4)
{
    int i = blockIdx.x * blockDim.x + threadIdx.x;
    if (i >= n4) return;
    float4 v = src[i];
    float hx = __bfloat162float(__float2bfloat16(v.x));
    float hy = __bfloat162float(__float2bfloat16(v.y));
    float hz = __bfloat162float(__float2bfloat16(v.z));
    float hw = __bfloat162float(__float2bfloat16(v.w));
    uint2 H, L;
    H.x = pack_bf2(v.x, v.y);           H.y = pack_bf2(v.z, v.w);
    L.x = pack_bf2(v.x - hx, v.y - hy); L.y = pack_bf2(v.z - hz, v.w - hw);
    hi[i] = H; lo[i] = L;
}

// W_x (2048 x 96) -> padded bf16 hi/lo (2048 x 128), cols 96.. zero
__global__ void cvt_wx_kernel(const float* __restrict__ W,
                              __nv_bfloat16* __restrict__ hi,
                              __nv_bfloat16* __restrict__ lo)
{
    int i = blockIdx.x * blockDim.x + threadIdx.x;
    if (i >= DI * NDP) return;
    int r = i >> 7, c = i & 127;
    float v = (c < 96) ? W[r * 96 + c] : 0.f;
    __nv_bfloat16 h = __float2bfloat16(v);
    hi[i] = h;
    lo[i] = __float2bfloat16(v - __bfloat162float(h));
}

// sum 8 K-split partial slabs -> dbl, and emit compact bf16 hi/lo of cols 0..63
__global__ void reduce_dbl_kernel(const float* __restrict__ parts,
                                  float* __restrict__ dbl,
                                  __nv_bfloat16* __restrict__ dbh,
                                  __nv_bfloat16* __restrict__ dbll)
{
    int i = blockIdx.x * blockDim.x + threadIdx.x;
    if (i >= MROWS * NDP) return;
    float s = 0.f;
#pragma unroll
    for (int k = 0; k < 8; k++) s += parts[(size_t)k * MROWS * NDP + i];
    dbl[i] = s;
    int c = i & 127;
    if (c < 64) {
        int r = i >> 7;
        __nv_bfloat16 h = __float2bfloat16(s);
        dbh [r * DTR + c] = h;
        dbll[r * DTR + c] = __float2bfloat16(s - __bfloat162float(h));
    }
}

// ---------------------------------------------------------------------------
// Tensor-core GEMM, bf16 split-3: C = AhBh + AlBh + AhBl
// 128x128 block tile, BK=16, 3-stage cp.async, term-major MMA ordering.
// Optional K-split (blockIdx.z) and fused bias+softplus epilogue.
// ---------------------------------------------------------------------------
#define AS_ST 24
#define BS_ST 136
#define A_PLANE (128*AS_ST)
#define B_PLANE (16*BS_ST)
#define AH_OFF 0
#define AL_OFF A_PLANE
#define BH_OFF (2*A_PLANE)
#define BL_OFF (2*A_PLANE + B_PLANE)
#define STAGE_SZ (2*A_PLANE + 2*B_PLANE)        // elems
#define STAGE_B  (STAGE_SZ*2)                   // bytes: 20992
#define SMEM_TOT (3*STAGE_B)                    // 62976

__device__ __forceinline__ void cp16(uint32_t dst, const void* src) {
    asm volatile("cp.async.cg.shared.global [%0], [%1], 16;\n" :: "r"(dst), "l"(src));
}
__device__ __forceinline__ void ldsm4(uint32_t* r, uint32_t addr) {
    asm volatile("ldmatrix.sync.aligned.m8n8.x4.shared.b16 {%0,%1,%2,%3}, [%4];"
                 : "=r"(r[0]), "=r"(r[1]), "=r"(r[2]), "=r"(r[3]) : "r"(addr));
}
__device__ __forceinline__ void ldsm4t(uint32_t* r, uint32_t addr) {
    asm volatile("ldmatrix.sync.aligned.m8n8.x4.trans.shared.b16 {%0,%1,%2,%3}, [%4];"
                 : "=r"(r[0]), "=r"(r[1]), "=r"(r[2]), "=r"(r[3]) : "r"(addr));
}
__device__ __forceinline__ void mma_bf16(float* c, const uint32_t* a, const uint32_t* b) {
    asm volatile("mma.sync.aligned.m16n8k16.row.col.f32.bf16.bf16.f32 "
                 "{%0,%1,%2,%3},{%4,%5,%6,%7},{%8,%9},{%0,%1,%2,%3};"
                 : "+f"(c[0]), "+f"(c[1]), "+f"(c[2]), "+f"(c[3])
                 : "r"(a[0]), "r"(a[1]), "r"(a[2]), "r"(a[3]), "r"(b[0]), "r"(b[1]));
}

__global__ __launch_bounds__(256, 2)
void mma_gemm(const __nv_bfloat16* __restrict__ Ah, const __nv_bfloat16* __restrict__ Al,
              const __nv_bfloat16* __restrict__ Bh, const __nv_bfloat16* __restrict__ Bl,
              float* __restrict__ C, int Kchunk,
              int lda, int ldb, int ldc,
              size_t slabStride,
              const float* __restrict__ bias)
{
    extern __shared__ __align__(16) char dynsmem[];
    __nv_bfloat16* smem = reinterpret_cast<__nv_bfloat16*>(dynsmem);

    const int tid  = threadIdx.x;
    const int lane = tid & 31;
    const int wid  = tid >> 5;
    const int wm   = (wid >> 2) * 64;
    const int wn   = (wid & 3) * 32;
    const int bm   = blockIdx.y * 128;
    const int bn   = blockIdx.x * 128;
    const int kb   = blockIdx.z * Kchunk;

    C += (size_t)blockIdx.z * slabStride;

    const int ar = tid >> 1,  ac = (tid & 1) * 8;
    const int br = tid >> 4,  bc = (tid & 15) * 8;

    const uint32_t sbase = (uint32_t)__cvta_generic_to_shared(smem);

    float acc[4][4][4];
#pragma unroll
    for (int i = 0; i < 4; i++)
#pragma unroll
        for (int j = 0; j < 4; j++)
#pragma unroll
            for (int k = 0; k < 4; k++) acc[i][j][k] = 0.f;

    const int KT = Kchunk >> 4;

    const __nv_bfloat16* Abh = Ah + (size_t)(bm + ar) * lda + kb + ac;
    const __nv_bfloat16* Abl = Al + (size_t)(bm + ar) * lda + kb + ac;
    const __nv_bfloat16* Bbh = Bh + (size_t)(kb + br) * ldb + bn + bc;
    const __nv_bfloat16* Bbl = Bl + (size_t)(kb + br) * ldb + bn + bc;

#define ISSUE(stage, kt_) {                                                   \
        uint32_t sb = sbase + (stage) * STAGE_B;                              \
        int k0 = (kt_) << 4;                                                  \
        cp16(sb + (AH_OFF + ar * AS_ST + ac) * 2, Abh + k0);                  \
        cp16(sb + (AL_OFF + ar * AS_ST + ac) * 2, Abl + k0);                  \
        cp16(sb + (BH_OFF + br * BS_ST + bc) * 2, Bbh + (size_t)k0 * ldb);    \
        cp16(sb + (BL_OFF + br * BS_ST + bc) * 2, Bbl + (size_t)k0 * ldb);    \
    }

    ISSUE(0, 0);
    asm volatile("cp.async.commit_group;\n");
    if (KT > 1) ISSUE(1, 1);
    asm volatile("cp.async.commit_group;\n");

    const int arow = lane & 15;
    const int acol = (lane >> 4) * 8;

    for (int kt = 0; kt < KT; ++kt) {
        asm volatile("cp.async.wait_group 1;\n");
        __syncthreads();

        if (kt + 2 < KT) ISSUE((kt + 2) % 3, kt + 2);
        asm volatile("cp.async.commit_group;\n");

        uint32_t sb = sbase + (kt % 3) * STAGE_B;
        uint32_t ah[4][4], al[4][4], bx[4][2];

        // --- ldsm Ah + Bh ---
#pragma unroll
        for (int i = 0; i < 4; i++) {
            uint32_t off = (uint32_t)((wm + i * 16 + arow) * AS_ST + acol) * 2;
            ldsm4(ah[i], sb + AH_OFF * 2 + off);
        }
#pragma unroll
        for (int jj = 0; jj < 2; jj++) {
            uint32_t off = (uint32_t)(arow * BS_ST + wn + jj * 16 + acol) * 2;
            uint32_t r[4];
            ldsm4t(r, sb + BH_OFF * 2 + off);
            bx[2 * jj][0] = r[0]; bx[2 * jj][1] = r[1];
            bx[2 * jj + 1][0] = r[2]; bx[2 * jj + 1][1] = r[3];
        }
        // --- term 1: Ah x Bh (16 independent MMAs) ---
#pragma unroll
        for (int i = 0; i < 4; i++)
#pragma unroll
            for (int j = 0; j < 4; j++) mma_bf16(acc[i][j], ah[i], bx[j]);

        // --- ldsm Al, then term 2: Al x Bh ---
#pragma unroll
        for (int i = 0; i < 4; i++) {
            uint32_t off = (uint32_t)((wm + i * 16 + arow) * AS_ST + acol) * 2;
            ldsm4(al[i], sb + AL_OFF * 2 + off);
        }
#pragma unroll
        for (int i = 0; i < 4; i++)
#pragma unroll
            for (int j = 0; j < 4; j++) mma_bf16(acc[i][j], al[i], bx[j]);

        // --- ldsm Bl (reuse bx regs), then term 3: Ah x Bl ---
#pragma unroll
        for (int jj = 0; jj < 2; jj++) {
            uint32_t off = (uint32_t)(arow * BS_ST + wn + jj * 16 + acol) * 2;
            uint32_t r[4];
            ldsm4t(r, sb + BL_OFF * 2 + off);
            bx[2 * jj][0] = r[0]; bx[2 * jj][1] = r[1];
            bx[2 * jj + 1][0] = r[2]; bx[2 * jj + 1][1] = r[3];
        }
#pragma unroll
        for (int i = 0; i < 4; i++)
#pragma unroll
            for (int j = 0; j < 4; j++) mma_bf16(acc[i][j], ah[i], bx[j]);
    }
#undef ISSUE

    const bool sp = (bias != nullptr);
#pragma unroll
    for (int i = 0; i < 4; i++) {
        int row0 = bm + wm + i * 16 + (lane >> 2);
#pragma unroll
        for (int j = 0; j < 4; j++) {
            int col = bn + wn + j * 8 + (lane & 3) * 2;
            float v0 = acc[i][j][0], v1 = acc[i][j][1];
            float v2 = acc[i][j][2], v3 = acc[i][j][3];
            if (sp) {
                float b0 = bias[col], b1 = bias[col + 1];
                v0 += b0; v1 += b1; v2 += b0; v3 += b1;
                v0 = (v0 > 20.f) ? v0 : log1pf(__expf(v0));
                v1 = (v1 > 20.f) ? v1 : log1pf(__expf(v1));
                v2 = (v2 > 20.f) ? v2 : log1pf(__expf(v2));
                v3 = (v3 > 20.f) ? v3 : log1pf(__expf(v3));
            }
            *(float2*)(C + (size_t)row0 * ldc + col)       = make_float2(v0, v1);
            *(float2*)(C + (size_t)(row0 + 8) * ldc + col) = make_float2(v2, v3);
        }
    }
}

// ---------------------------------------------------------------------------
// Depthwise causal conv (width 4) + bias + SiLU; emits fp32 + bf16 hi/lo.
// ---------------------------------------------------------------------------
__global__ void conv_silu_kernel(const float* __restrict__ xz,
                                 const float* __restrict__ conv_w,
                                 const float* __restrict__ conv_b,
                                 float* __restrict__ xc,
                                 __nv_bfloat16* __restrict__ xch,
                                 __nv_bfloat16* __restrict__ xcl)
{
    int idx = blockIdx.x * blockDim.x + threadIdx.x;
    if (idx >= MROWS * DI) return;
    int d = idx & (DI - 1);
    int l = (idx >> 11) & (LC - 1);
    int b = idx >> 21;

    float acc = conv_b[d];
#pragma unroll
    for (int j = 0; j < DCNV; j++) {
        int ll = l + j - (DCNV - 1);
        if (ll >= 0)
            acc += xz[(size_t)(b * LC + ll) * NXZ + d] * conv_w[d * DCNV + j];
    }
    float v = acc / (1.f + __expf(-acc));
    xc[idx] = v;
    __nv_bfloat16 h = __float2bfloat16(v);
    xch[idx] = h;
    xcl[idx] = __float2bfloat16(v - __bfloat162float(h));
}

// ---------------------------------------------------------------------------
// Selective scan: 8 lanes/channel, 2 states/lane, depth-1 prefetch.
// ---------------------------------------------------------------------------
__global__ __launch_bounds__(256)
void scan_kernel(const float* __restrict__ dt,
                 const float* __restrict__ xc,
                 const float* __restrict__ dbl,
                 const float* __restrict__ xz,
                 const float* __restrict__ A_log,
                 const float* __restrict__ D_par,
                 __nv_bfloat16* __restrict__ yh,
                 __nv_bfloat16* __restrict__ yl)
{
    const int gtid = blockIdx.x * 256 + threadIdx.x;
    const int ch = gtid >> 3;
    const int nl = gtid & 7;
    const int n0 = nl * 2;
    const int b  = ch >> 11;
    const int d  = ch & (DI - 1);

    const float An0 = -expf(A_log[d * DS + n0]);
    const float An1 = -expf(A_log[d * DS + n0 + 1]);
    const float Dv  = D_par[d];
    float h0 = 0.f, h1 = 0.f;

    const size_t rowbase = (size_t)b * LC;
    const float* pdt = dt  + rowbase * DI + d;
    const float* pxc = xc  + rowbase * DI + d;
    const float* pBC = dbl + rowbase * NDP + 64 + n0;
    const float* pz  = xz  + rowbase * NXZ + DI + d;
    __nv_bfloat16* pyh = yh + rowbase * DI + d;
    __nv_bfloat16* pyl = yl + rowbase * DI + d;

    float  dtv = __ldg(pdt);
    float  xcv = __ldg(pxc);
    float2 Bv  = __ldg((const float2*)pBC);
    float2 Cv  = __ldg((const float2*)(pBC + DS));
    float  zv  = (nl == 0) ? __ldg(pz) : 0.f;

    for (int l = 0; l < LC; ++l) {
        int lp = (l + 1 < LC) ? (l + 1) : l;
        float  dtn = __ldg(pdt + (size_t)lp * DI);
        float  xcn = __ldg(pxc + (size_t)lp * DI);
        float2 Bn  = __ldg((const float2*)(pBC + (size_t)lp * NDP));
        float2 Cn  = __ldg((const float2*)(pBC + (size_t)lp * NDP + DS));
        float  zn  = (nl == 0) ? __ldg(pz + (size_t)lp * NXZ) : 0.f;

        float dx = dtv * xcv;
        h0 = __expf(dtv * An0) * h0 + dx * Bv.x;
        h1 = __expf(dtv * An1) * h1 + dx * Bv.y;

        float yv = h0 * Cv.x + h1 * Cv.y;
        yv += __shfl_xor_sync(0xffffffffu, yv, 4);
        yv += __shfl_xor_sync(0xffffffffu, yv, 2);
        yv += __shfl_xor_sync(0xffffffffu, yv, 1);

        if (nl == 0) {
            float sil = zv / (1.f + __expf(-zv));
            float yo  = (yv + xcv * Dv) * sil;
            __nv_bfloat16 hh = __float2bfloat16(yo);
            pyh[(size_t)l * DI] = hh;
            pyl[(size_t)l * DI] = __float2bfloat16(yo - __bfloat162float(hh));
        }
        dtv = dtn; xcv = xcn; Bv = Bn; Cv = Cn; zv = zn;
    }
}

// ---------------------------------------------------------------------------
extern "C" void kernel_launch(void* const* d_in, const int* in_sizes, int n_in,
                              void* d_out, int out_size)
{
    const float* x      = (const float*)d_in[0];
    const float* W_in   = (const float*)d_in[1];
    const float* conv_w = (const float*)d_in[2];
    const float* conv_b = (const float*)d_in[3];
    const float* W_x    = (const float*)d_in[4];
    const float* W_dt   = (const float*)d_in[5];
    const float* b_dt   = (const float*)d_in[6];
    const float* A_log  = (const float*)d_in[7];
    const float* D_par  = (const float*)d_in[8];
    const float* W_out  = (const float*)d_in[9];
    float* out = (float*)d_out;

    float *xz, *xc, *dtb, *dbl, *dblp;
    __nv_bfloat16 *xh, *xl, *Wih, *Wil, *Wxh, *Wxl, *xch, *xcl,
                  *dbh, *dbll, *Wdh, *Wdl, *yh, *yl, *Woh, *Wol;
    cudaGetSymbolAddress((void**)&xz,   g_xz);
    cudaGetSymbolAddress((void**)&xc,   g_xc);
    cudaGetSymbolAddress((void**)&dtb,  g_dt);
    cudaGetSymbolAddress((void**)&dbl,  g_dbl);
    cudaGetSymbolAddress((void**)&dblp, g_dblp);
    cudaGetSymbolAddress((void**)&xh,   g_xh);   cudaGetSymbolAddress((void**)&xl,   g_xl);
    cudaGetSymbolAddress((void**)&Wih,  g_Wih);  cudaGetSymbolAddress((void**)&Wil,  g_Wil);
    cudaGetSymbolAddress((void**)&Wxh,  g_Wxh);  cudaGetSymbolAddress((void**)&Wxl,  g_Wxl);
    cudaGetSymbolAddress((void**)&xch,  g_xch);  cudaGetSymbolAddress((void**)&xcl,  g_xcl);
    cudaGetSymbolAddress((void**)&dbh,  g_dbh);  cudaGetSymbolAddress((void**)&dbll, g_dbll);
    cudaGetSymbolAddress((void**)&Wdh,  g_Wdh);  cudaGetSymbolAddress((void**)&Wdl,  g_Wdl);
    cudaGetSymbolAddress((void**)&yh,   g_yh);   cudaGetSymbolAddress((void**)&yl,   g_yl);
    cudaGetSymbolAddress((void**)&Woh,  g_Woh);  cudaGetSymbolAddress((void**)&Wol,  g_Wol);

    cudaFuncSetAttribute(mma_gemm, cudaFuncAttributeMaxDynamicSharedMemorySize, SMEM_TOT);

    // conversions (vectorized)
    cvt4_kernel<<<(MROWS * DM / 4 + 255) / 256, 256>>>((const float4*)x, (uint2*)xh, (uint2*)xl, MROWS * DM / 4);
    cvt4_kernel<<<(DM * NXZ / 4 + 255) / 256, 256>>>((const float4*)W_in, (uint2*)Wih, (uint2*)Wil, DM * NXZ / 4);
    cvt4_kernel<<<(DTR * DI / 4 + 255) / 256, 256>>>((const float4*)W_dt, (uint2*)Wdh, (uint2*)Wdl, DTR * DI / 4);
    cvt4_kernel<<<(DI * DM / 4 + 255) / 256, 256>>>((const float4*)W_out, (uint2*)Woh, (uint2*)Wol, DI * DM / 4);
    cvt_wx_kernel<<<(DI * NDP + 255) / 256, 256>>>(W_x, Wxh, Wxl);

    // 1) xz = x @ W_in
    mma_gemm<<<dim3(NXZ / 128, MROWS / 128, 1), 256, SMEM_TOT>>>(
        xh, xl, Wih, Wil, xz, DM, DM, NXZ, NXZ, 0, nullptr);

    // 2) conv + SiLU (+ bf16 split)
    conv_silu_kernel<<<(MROWS * DI) / 256, 256>>>(xz, conv_w, conv_b, xc, xch, xcl);

    // 3) dbl = xc @ W_x_padded, K-split 8
    mma_gemm<<<dim3(1, MROWS / 128, 8), 256, SMEM_TOT>>>(
        xch, xcl, Wxh, Wxl, dblp, DI / 8, DI, NDP, NDP,
        (size_t)MROWS * NDP, nullptr);

    // 4) reduce partials + compact bf16 of dt-rank slice
    reduce_dbl_kernel<<<(MROWS * NDP + 255) / 256, 256>>>(dblp, dbl, dbh, dbll);

    // 5) dt = softplus(dbl[:,:64] @ W_dt + b_dt)
    mma_gemm<<<dim3(DI / 128, MROWS / 128, 1), 256, SMEM_TOT>>>(
        dbh, dbll, Wdh, Wdl, dtb, DTR, DTR, DI, DI, 0, b_dt);

    // 6) selective scan -> y (bf16 hi/lo)
    scan_kernel<<<(BC * DI * 8) / 256, 256>>>(dtb, xc, dbl, xz, A_log, D_par, yh, yl);

    // 7) out = y @ W_out
    mma_gemm<<<dim3(DM / 128, MROWS / 128, 1), 256, SMEM_TOT>>>(
        yh, yl, Woh, Wol, out, DI, DI, DM, DM, 0, nullptr);
}

// round 6
// speedup vs baseline: 4.1787x; 1.9014x over previous
#include <cuda_runtime.h>
#include <cuda_fp16.h>
#include <cstdint>

// Problem dims (fixed)
#define BC   2
#define LC   1024
#define DM   1024
#define DI   2048
#define DS   16
#define DCNV 4
#define DTR  64
#define MROWS (BC*LC)      // 2048
#define NXZ   (2*DI)       // 4096
#define NDP   128          // padded dbl width

// ---------------- scratch (device globals; no runtime allocation) ----------
__device__ float g_xz  [MROWS * NXZ];       // 32 MB
__device__ float g_xc  [MROWS * DI];        // 16 MB
__device__ float g_dt  [MROWS * DI];        // 16 MB
__device__ float g_dbl [MROWS * NDP];       // 1 MB
__device__ float g_dblp[8 * MROWS * NDP];   // 8 MB (K-split partials)

__device__ __half g_xh  [MROWS * DM],  g_xl  [MROWS * DM];
__device__ __half g_Wih [DM * NXZ];                          // W_in hi only
__device__ __half g_Wxh [DI * NDP],    g_Wxl [DI * NDP];
__device__ __half g_xch [MROWS * DI],  g_xcl [MROWS * DI];
__device__ __half g_dbh [MROWS * DTR], g_dbll[MROWS * DTR];
__device__ __half g_Wdh [DTR * DI],    g_Wdl [DTR * DI];
__device__ __half g_yh  [MROWS * DI],  g_yl  [MROWS * DI];
__device__ __half g_Woh [DI * DM];                           // W_out hi only

// ---------------------------------------------------------------------------
// helpers
// ---------------------------------------------------------------------------
__device__ __forceinline__ uint32_t pack_h2(float a, float b) {
    __half2 h = __floats2half2_rn(a, b);
    return *reinterpret_cast<uint32_t*>(&h);
}

// fp32 -> fp16 hi/lo split, vectorized x4
__global__ void cvt4h_kernel(const float4* __restrict__ src,
                             uint2* __restrict__ hi, uint2* __restrict__ lo, int n4)
{
    int i = blockIdx.x * blockDim.x + threadIdx.x;
    if (i >= n4) return;
    float4 v = src[i];
    float hx = __half2float(__float2half(v.x));
    float hy = __half2float(__float2half(v.y));
    float hz = __half2float(__float2half(v.z));
    float hw = __half2float(__float2half(v.w));
    uint2 H, L;
    H.x = pack_h2(v.x, v.y);            H.y = pack_h2(v.z, v.w);
    L.x = pack_h2(v.x - hx, v.y - hy);  L.y = pack_h2(v.z - hz, v.w - hw);
    hi[i] = H; lo[i] = L;
}

// fp32 -> fp16 hi only, vectorized x4
__global__ void cvt4h1_kernel(const float4* __restrict__ src,
                              uint2* __restrict__ hi, int n4)
{
    int i = blockIdx.x * blockDim.x + threadIdx.x;
    if (i >= n4) return;
    float4 v = src[i];
    uint2 H;
    H.x = pack_h2(v.x, v.y); H.y = pack_h2(v.z, v.w);
    hi[i] = H;
}

// W_x (2048 x 96) -> padded fp16 hi/lo (2048 x 128), cols 96.. zero
__global__ void cvt_wx_kernel(const float* __restrict__ W,
                              __half* __restrict__ hi, __half* __restrict__ lo)
{
    int i = blockIdx.x * blockDim.x + threadIdx.x;
    if (i >= DI * NDP) return;
    int r = i >> 7, c = i & 127;
    float v = (c < 96) ? W[r * 96 + c] : 0.f;
    __half h = __float2half(v);
    hi[i] = h;
    lo[i] = __float2half(v - __half2float(h));
}

// sum 8 K-split partial slabs -> dbl, + compact fp16 hi/lo of cols 0..63
__global__ void reduce_dbl_kernel(const float* __restrict__ parts,
                                  float* __restrict__ dbl,
                                  __half* __restrict__ dbh,
                                  __half* __restrict__ dbll)
{
    int i = blockIdx.x * blockDim.x + threadIdx.x;
    if (i >= MROWS * NDP) return;
    float s = 0.f;
#pragma unroll
    for (int k = 0; k < 8; k++) s += parts[(size_t)k * MROWS * NDP + i];
    dbl[i] = s;
    int c = i & 127;
    if (c < 64) {
        int r = i >> 7;
        __half h = __float2half(s);
        dbh [r * DTR + c] = h;
        dbll[r * DTR + c] = __float2half(s - __half2float(h));
    }
}

// ---------------------------------------------------------------------------
// Tensor-core GEMM, fp16 split: 2-term (AhBh + AlBh) or 3-term (+ AhBl).
// 128x128 tile, BK=16, 3-stage cp.async, term-major MMA ordering.
// Optional K-split (blockIdx.z) and fused bias+softplus epilogue.
// ---------------------------------------------------------------------------
#define AS_ST 24
#define BS_ST 136
#define A_PLANE (128*AS_ST)
#define B_PLANE (16*BS_ST)

__device__ __forceinline__ void cp16(uint32_t dst, const void* src) {
    asm volatile("cp.async.cg.shared.global [%0], [%1], 16;\n" :: "r"(dst), "l"(src));
}
__device__ __forceinline__ void ldsm4(uint32_t* r, uint32_t addr) {
    asm volatile("ldmatrix.sync.aligned.m8n8.x4.shared.b16 {%0,%1,%2,%3}, [%4];"
                 : "=r"(r[0]), "=r"(r[1]), "=r"(r[2]), "=r"(r[3]) : "r"(addr));
}
__device__ __forceinline__ void ldsm4t(uint32_t* r, uint32_t addr) {
    asm volatile("ldmatrix.sync.aligned.m8n8.x4.trans.shared.b16 {%0,%1,%2,%3}, [%4];"
                 : "=r"(r[0]), "=r"(r[1]), "=r"(r[2]), "=r"(r[3]) : "r"(addr));
}
__device__ __forceinline__ void mma_f16(float* c, const uint32_t* a, const uint32_t* b) {
    asm volatile("mma.sync.aligned.m16n8k16.row.col.f32.f16.f16.f32 "
                 "{%0,%1,%2,%3},{%4,%5,%6,%7},{%8,%9},{%0,%1,%2,%3};"
                 : "+f"(c[0]), "+f"(c[1]), "+f"(c[2]), "+f"(c[3])
                 : "r"(a[0]), "r"(a[1]), "r"(a[2]), "r"(a[3]), "r"(b[0]), "r"(b[1]));
}

template<bool THREE>
__global__ __launch_bounds__(256, 2)
void mma_gemm(const __half* __restrict__ Ah, const __half* __restrict__ Al,
              const __half* __restrict__ Bh, const __half* __restrict__ Bl,
              float* __restrict__ C, int Kchunk,
              int lda, int ldb, int ldc,
              size_t slabStride,
              const float* __restrict__ bias)
{
    constexpr int AH_OFF = 0;
    constexpr int AL_OFF = A_PLANE;
    constexpr int BH_OFF = 2 * A_PLANE;
    constexpr int BL_OFF = 2 * A_PLANE + B_PLANE;
    constexpr uint32_t STAGE_B = (2 * A_PLANE + (THREE ? 2 : 1) * B_PLANE) * 2;

    extern __shared__ __align__(16) char dynsmem[];
    __half* smem = reinterpret_cast<__half*>(dynsmem);

    const int tid  = threadIdx.x;
    const int lane = tid & 31;
    const int wid  = tid >> 5;
    const int wm   = (wid >> 2) * 64;
    const int wn   = (wid & 3) * 32;
    const int bm   = blockIdx.y * 128;
    const int bn   = blockIdx.x * 128;
    const int kb   = blockIdx.z * Kchunk;

    C += (size_t)blockIdx.z * slabStride;

    const int ar = tid >> 1,  ac = (tid & 1) * 8;
    const int br = tid >> 4,  bc = (tid & 15) * 8;

    const uint32_t sbase = (uint32_t)__cvta_generic_to_shared(smem);

    float acc[4][4][4];
#pragma unroll
    for (int i = 0; i < 4; i++)
#pragma unroll
        for (int j = 0; j < 4; j++)
#pragma unroll
            for (int k = 0; k < 4; k++) acc[i][j][k] = 0.f;

    const int KT = Kchunk >> 4;

    const __half* Abh = Ah + (size_t)(bm + ar) * lda + kb + ac;
    const __half* Abl = Al + (size_t)(bm + ar) * lda + kb + ac;
    const __half* Bbh = Bh + (size_t)(kb + br) * ldb + bn + bc;
    const __half* Bbl = THREE ? (Bl + (size_t)(kb + br) * ldb + bn + bc) : nullptr;

#define ISSUE(stage, kt_) {                                                   \
        uint32_t sb = sbase + (stage) * STAGE_B;                              \
        int k0 = (kt_) << 4;                                                  \
        cp16(sb + (AH_OFF + ar * AS_ST + ac) * 2, Abh + k0);                  \
        cp16(sb + (AL_OFF + ar * AS_ST + ac) * 2, Abl + k0);                  \
        cp16(sb + (BH_OFF + br * BS_ST + bc) * 2, Bbh + (size_t)k0 * ldb);    \
        if (THREE)                                                            \
            cp16(sb + (BL_OFF + br * BS_ST + bc) * 2, Bbl + (size_t)k0 * ldb);\
    }

    ISSUE(0, 0);
    asm volatile("cp.async.commit_group;\n");
    if (KT > 1) ISSUE(1, 1);
    asm volatile("cp.async.commit_group;\n");

    const int arow = lane & 15;
    const int acol = (lane >> 4) * 8;

    for (int kt = 0; kt < KT; ++kt) {
        asm volatile("cp.async.wait_group 1;\n");
        __syncthreads();

        if (kt + 2 < KT) ISSUE((kt + 2) % 3, kt + 2);
        asm volatile("cp.async.commit_group;\n");

        uint32_t sb = sbase + (kt % 3) * STAGE_B;
        uint32_t ah[4][4], al[4][4], bx[4][2];

        // ldsm Ah + Bh
#pragma unroll
        for (int i = 0; i < 4; i++) {
            uint32_t off = (uint32_t)((wm + i * 16 + arow) * AS_ST + acol) * 2;
            ldsm4(ah[i], sb + AH_OFF * 2 + off);
        }
#pragma unroll
        for (int jj = 0; jj < 2; jj++) {
            uint32_t off = (uint32_t)(arow * BS_ST + wn + jj * 16 + acol) * 2;
            uint32_t r[4];
            ldsm4t(r, sb + BH_OFF * 2 + off);
            bx[2 * jj][0] = r[0]; bx[2 * jj][1] = r[1];
            bx[2 * jj + 1][0] = r[2]; bx[2 * jj + 1][1] = r[3];
        }
        // term 1: Ah x Bh
#pragma unroll
        for (int i = 0; i < 4; i++)
#pragma unroll
            for (int j = 0; j < 4; j++) mma_f16(acc[i][j], ah[i], bx[j]);

        // ldsm Al, term 2: Al x Bh
#pragma unroll
        for (int i = 0; i < 4; i++) {
            uint32_t off = (uint32_t)((wm + i * 16 + arow) * AS_ST + acol) * 2;
            ldsm4(al[i], sb + AL_OFF * 2 + off);
        }
#pragma unroll
        for (int i = 0; i < 4; i++)
#pragma unroll
            for (int j = 0; j < 4; j++) mma_f16(acc[i][j], al[i], bx[j]);

        if (THREE) {
            // ldsm Bl (reuse bx), term 3: Ah x Bl
#pragma unroll
            for (int jj = 0; jj < 2; jj++) {
                uint32_t off = (uint32_t)(arow * BS_ST + wn + jj * 16 + acol) * 2;
                uint32_t r[4];
                ldsm4t(r, sb + BL_OFF * 2 + off);
                bx[2 * jj][0] = r[0]; bx[2 * jj][1] = r[1];
                bx[2 * jj + 1][0] = r[2]; bx[2 * jj + 1][1] = r[3];
            }
#pragma unroll
            for (int i = 0; i < 4; i++)
#pragma unroll
                for (int j = 0; j < 4; j++) mma_f16(acc[i][j], ah[i], bx[j]);
        }
    }
#undef ISSUE

    const bool sp = (bias != nullptr);
#pragma unroll
    for (int i = 0; i < 4; i++) {
        int row0 = bm + wm + i * 16 + (lane >> 2);
#pragma unroll
        for (int j = 0; j < 4; j++) {
            int col = bn + wn + j * 8 + (lane & 3) * 2;
            float v0 = acc[i][j][0], v1 = acc[i][j][1];
            float v2 = acc[i][j][2], v3 = acc[i][j][3];
            if (sp) {
                float b0 = bias[col], b1 = bias[col + 1];
                v0 += b0; v1 += b1; v2 += b0; v3 += b1;
                v0 = (v0 > 20.f) ? v0 : log1pf(__expf(v0));
                v1 = (v1 > 20.f) ? v1 : log1pf(__expf(v1));
                v2 = (v2 > 20.f) ? v2 : log1pf(__expf(v2));
                v3 = (v3 > 20.f) ? v3 : log1pf(__expf(v3));
            }
            *(float2*)(C + (size_t)row0 * ldc + col)       = make_float2(v0, v1);
            *(float2*)(C + (size_t)(row0 + 8) * ldc + col) = make_float2(v2, v3);
        }
    }
}

// ---------------------------------------------------------------------------
// Depthwise causal conv (width 4) + bias + SiLU; emits fp32 + fp16 hi/lo.
// ---------------------------------------------------------------------------
__global__ void conv_silu_kernel(const float* __restrict__ xz,
                                 const float* __restrict__ conv_w,
                                 const float* __restrict__ conv_b,
                                 float* __restrict__ xc,
                                 __half* __restrict__ xch,
                                 __half* __restrict__ xcl)
{
    int idx = blockIdx.x * blockDim.x + threadIdx.x;
    if (idx >= MROWS * DI) return;
    int d = idx & (DI - 1);
    int l = (idx >> 11) & (LC - 1);
    int b = idx >> 21;

    float acc = conv_b[d];
#pragma unroll
    for (int j = 0; j < DCNV; j++) {
        int ll = l + j - (DCNV - 1);
        if (ll >= 0)
            acc += xz[(size_t)(b * LC + ll) * NXZ + d] * conv_w[d * DCNV + j];
    }
    float v = acc / (1.f + __expf(-acc));
    xc[idx] = v;
    __half h = __float2half(v);
    xch[idx] = h;
    xcl[idx] = __float2half(v - __half2float(h));
}

// ---------------------------------------------------------------------------
// Selective scan: 8 lanes/channel, 2 states/lane.
// Chunk-4 register double buffering: loads for chunk g+1 issued before
// computing chunk g, so ~L2 latency is hidden behind 4 recurrence steps.
// ---------------------------------------------------------------------------
#define SCH 4
__global__ __launch_bounds__(256)
void scan_kernel(const float* __restrict__ dt,
                 const float* __restrict__ xc,
                 const float* __restrict__ dbl,
                 const float* __restrict__ xz,
                 const float* __restrict__ A_log,
                 const float* __restrict__ D_par,
                 __half* __restrict__ yh,
                 __half* __restrict__ yl)
{
    const int gtid = blockIdx.x * 256 + threadIdx.x;
    const int ch = gtid >> 3;
    const int nl = gtid & 7;
    const int n0 = nl * 2;
    const int b  = ch >> 11;
    const int d  = ch & (DI - 1);

    const float An0 = -expf(A_log[d * DS + n0]);
    const float An1 = -expf(A_log[d * DS + n0 + 1]);
    const float Dv  = D_par[d];
    float h0 = 0.f, h1 = 0.f;

    const size_t rowbase = (size_t)b * LC;
    const float* pdt = dt  + rowbase * DI + d;
    const float* pxc = xc  + rowbase * DI + d;
    const float* pBC = dbl + rowbase * NDP + 64 + n0;
    const float* pz  = xz  + rowbase * NXZ + DI + d;
    __half* pyh = yh + rowbase * DI + d;
    __half* pyl = yl + rowbase * DI + d;

    float  dtb_[2][SCH], xcb[2][SCH], zb[2][SCH];
    float2 Bb[2][SCH], Cb[2][SCH];

#define LOADG(g_, p_) {                                                        \
        _Pragma("unroll")                                                      \
        for (int u = 0; u < SCH; u++) {                                        \
            size_t row = (size_t)((g_) * SCH + u);                             \
            dtb_[p_][u] = __ldg(pdt + row * DI);                               \
            xcb[p_][u]  = __ldg(pxc + row * DI);                               \
            Bb[p_][u]   = __ldg((const float2*)(pBC + row * NDP));             \
            Cb[p_][u]   = __ldg((const float2*)(pBC + row * NDP + DS));        \
            zb[p_][u]   = (nl == 0) ? __ldg(pz + row * NXZ) : 0.f;             \
        }                                                                      \
    }

    const int NG = LC / SCH;       // 256
    LOADG(0, 0);

#pragma unroll 2
    for (int g = 0; g < NG; g++) {
        const int p = g & 1;
        if (g + 1 < NG) LOADG(g + 1, p ^ 1);

#pragma unroll
        for (int u = 0; u < SCH; u++) {
            float dtv = dtb_[p][u], xcv = xcb[p][u];
            float2 Bv = Bb[p][u],   Cv  = Cb[p][u];

            float dx = dtv * xcv;
            h0 = __expf(dtv * An0) * h0 + dx * Bv.x;
            h1 = __expf(dtv * An1) * h1 + dx * Bv.y;

            float yv = h0 * Cv.x + h1 * Cv.y;
            yv += __shfl_xor_sync(0xffffffffu, yv, 4);
            yv += __shfl_xor_sync(0xffffffffu, yv, 2);
            yv += __shfl_xor_sync(0xffffffffu, yv, 1);

            if (nl == 0) {
                float zv  = zb[p][u];
                float sil = zv / (1.f + __expf(-zv));
                float yo  = (yv + xcv * Dv) * sil;
                size_t row = (size_t)(g * SCH + u);
                __half hh = __float2half(yo);
                pyh[row * DI] = hh;
                pyl[row * DI] = __float2half(yo - __half2float(hh));
            }
        }
    }
#undef LOADG
}

// ---------------------------------------------------------------------------
extern "C" void kernel_launch(void* const* d_in, const int* in_sizes, int n_in,
                              void* d_out, int out_size)
{
    const float* x      = (const float*)d_in[0];
    const float* W_in   = (const float*)d_in[1];
    const float* conv_w = (const float*)d_in[2];
    const float* conv_b = (const float*)d_in[3];
    const float* W_x    = (const float*)d_in[4];
    const float* W_dt   = (const float*)d_in[5];
    const float* b_dt   = (const float*)d_in[6];
    const float* A_log  = (const float*)d_in[7];
    const float* D_par  = (const float*)d_in[8];
    const float* W_out  = (const float*)d_in[9];
    float* out = (float*)d_out;

    float *xz, *xc, *dtb, *dbl, *dblp;
    __half *xh, *xl, *Wih, *Wxh, *Wxl, *xch, *xcl,
           *dbh, *dbll, *Wdh, *Wdl, *yh, *yl, *Woh;
    cudaGetSymbolAddress((void**)&xz,   g_xz);
    cudaGetSymbolAddress((void**)&xc,   g_xc);
    cudaGetSymbolAddress((void**)&dtb,  g_dt);
    cudaGetSymbolAddress((void**)&dbl,  g_dbl);
    cudaGetSymbolAddress((void**)&dblp, g_dblp);
    cudaGetSymbolAddress((void**)&xh,   g_xh);   cudaGetSymbolAddress((void**)&xl,   g_xl);
    cudaGetSymbolAddress((void**)&Wih,  g_Wih);
    cudaGetSymbolAddress((void**)&Wxh,  g_Wxh);  cudaGetSymbolAddress((void**)&Wxl,  g_Wxl);
    cudaGetSymbolAddress((void**)&xch,  g_xch);  cudaGetSymbolAddress((void**)&xcl,  g_xcl);
    cudaGetSymbolAddress((void**)&dbh,  g_dbh);  cudaGetSymbolAddress((void**)&dbll, g_dbll);
    cudaGetSymbolAddress((void**)&Wdh,  g_Wdh);  cudaGetSymbolAddress((void**)&Wdl,  g_Wdl);
    cudaGetSymbolAddress((void**)&yh,   g_yh);   cudaGetSymbolAddress((void**)&yl,   g_yl);
    cudaGetSymbolAddress((void**)&Woh,  g_Woh);

    const int SMEM2 = 3 * (2 * A_PLANE + 1 * B_PLANE) * 2;   // 2-term stages
    const int SMEM3 = 3 * (2 * A_PLANE + 2 * B_PLANE) * 2;   // 3-term stages
    cudaFuncSetAttribute(mma_gemm<false>, cudaFuncAttributeMaxDynamicSharedMemorySize, SMEM2);
    cudaFuncSetAttribute(mma_gemm<true>,  cudaFuncAttributeMaxDynamicSharedMemorySize, SMEM3);

    // conversions
    cvt4h_kernel<<<(MROWS * DM / 4 + 255) / 256, 256>>>((const float4*)x, (uint2*)xh, (uint2*)xl, MROWS * DM / 4);
    cvt4h1_kernel<<<(DM * NXZ / 4 + 255) / 256, 256>>>((const float4*)W_in, (uint2*)Wih, DM * NXZ / 4);
    cvt4h_kernel<<<(DTR * DI / 4 + 255) / 256, 256>>>((const float4*)W_dt, (uint2*)Wdh, (uint2*)Wdl, DTR * DI / 4);
    cvt4h1_kernel<<<(DI * DM / 4 + 255) / 256, 256>>>((const float4*)W_out, (uint2*)Woh, DI * DM / 4);
    cvt_wx_kernel<<<(DI * NDP + 255) / 256, 256>>>(W_x, Wxh, Wxl);

    // 1) xz = x @ W_in   (2-term)
    mma_gemm<false><<<dim3(NXZ / 128, MROWS / 128, 1), 256, SMEM2>>>(
        xh, xl, Wih, nullptr, xz, DM, DM, NXZ, NXZ, 0, nullptr);

    // 2) conv + SiLU (+ fp16 split)
    conv_silu_kernel<<<(MROWS * DI) / 256, 256>>>(xz, conv_w, conv_b, xc, xch, xcl);

    // 3) dbl = xc @ W_x_padded (3-term), K-split 8
    mma_gemm<true><<<dim3(1, MROWS / 128, 8), 256, SMEM3>>>(
        xch, xcl, Wxh, Wxl, dblp, DI / 8, DI, NDP, NDP,
        (size_t)MROWS * NDP, nullptr);

    // 4) reduce partials + compact fp16 of dt-rank slice
    reduce_dbl_kernel<<<(MROWS * NDP + 255) / 256, 256>>>(dblp, dbl, dbh, dbll);

    // 5) dt = softplus(dbl[:,:64] @ W_dt + b_dt)   (3-term)
    mma_gemm<true><<<dim3(DI / 128, MROWS / 128, 1), 256, SMEM3>>>(
        dbh, dbll, Wdh, Wdl, dtb, DTR, DTR, DI, DI, 0, b_dt);

    // 6) selective scan -> y (fp16 hi/lo)
    scan_kernel<<<(BC * DI * 8) / 256, 256>>>(dtb, xc, dbl, xz, A_log, D_par, yh, yl);

    // 7) out = y @ W_out   (2-term)
    mma_gemm<false><<<dim3(DM / 128, MROWS / 128, 1), 256, SMEM2>>>(
        yh, yl, Woh, nullptr, out, DI, DI, DM, DM, 0, nullptr);
}

// round 7
// speedup vs baseline: 4.3007x; 1.0292x over previous
#include <cuda_runtime.h>
#include <cuda_fp16.h>
#include <cstdint>

// Problem dims (fixed)
#define BC   2
#define LC   1024
#define DM   1024
#define DI   2048
#define DS   16
#define DCNV 4
#define DTR  64
#define MROWS (BC*LC)      // 2048
#define NXZ   (2*DI)       // 4096
#define NDP   128

// ---------------- scratch (device globals) ----------------
__device__ float g_xz  [MROWS * NXZ];
__device__ float g_xc  [MROWS * DI];
__device__ float g_dt  [MROWS * DI];
__device__ float g_dbl [MROWS * NDP];
__device__ float g_dblp[8 * MROWS * NDP];
__device__ float g_osp [2 * MROWS * DM];     // G4 split-K slabs

__device__ __half g_xh  [MROWS * DM],  g_xl  [MROWS * DM];
__device__ __half g_Wih [DM * NXZ];
__device__ __half g_Wxh [DI * NDP],    g_Wxl [DI * NDP];
__device__ __half g_xch [MROWS * DI],  g_xcl [MROWS * DI];
__device__ __half g_dbh [MROWS * DTR], g_dbll[MROWS * DTR];
__device__ __half g_Wdh [DTR * DI],    g_Wdl [DTR * DI];
__device__ __half g_yh  [MROWS * DI],  g_yl  [MROWS * DI];
__device__ __half g_Woh [DI * DM];

// ---------------------------------------------------------------------------
// helpers
// ---------------------------------------------------------------------------
__device__ __forceinline__ uint32_t pack_h2(float a, float b) {
    __half2 h = __floats2half2_rn(a, b);
    return *reinterpret_cast<uint32_t*>(&h);
}

// ---------------------------------------------------------------------------
// Fused conversion: one kernel covers all 5 input conversions.
// Unit = 4 fp32 elements. Segment map (in float4 units):
//   [0,        524288)  : x      -> xh, xl (hi/lo)
//   [524288,  1572864)  : W_in   -> Wih (hi only)
//   [1572864, 1605632)  : W_dt   -> Wdh, Wdl
//   [1605632, 2129920)  : W_out  -> Woh (hi only)
//   [2129920, 2195456)  : W_x    -> Wxh, Wxl padded [DI x 128], cols 96.. zero
// ---------------------------------------------------------------------------
#define SEG1  524288
#define SEG2 1572864
#define SEG3 1605632
#define SEG4 2129920
#define SEG5 2195456

__device__ __forceinline__ void split4(float4 v, uint2& H, uint2& L) {
    float hx = __half2float(__float2half(v.x));
    float hy = __half2float(__float2half(v.y));
    float hz = __half2float(__float2half(v.z));
    float hw = __half2float(__float2half(v.w));
    H.x = pack_h2(v.x, v.y);            H.y = pack_h2(v.z, v.w);
    L.x = pack_h2(v.x - hx, v.y - hy);  L.y = pack_h2(v.z - hz, v.w - hw);
}

__global__ void prep_kernel(const float4* __restrict__ x,
                            const float4* __restrict__ W_in,
                            const float4* __restrict__ W_dt,
                            const float4* __restrict__ W_out,
                            const float*  __restrict__ W_x,
                            uint2* __restrict__ xh,  uint2* __restrict__ xl,
                            uint2* __restrict__ Wih,
                            uint2* __restrict__ Wdh, uint2* __restrict__ Wdl,
                            uint2* __restrict__ Woh,
                            uint2* __restrict__ Wxh, uint2* __restrict__ Wxl)
{
    int i = blockIdx.x * blockDim.x + threadIdx.x;
    if (i >= SEG5) return;
    if (i < SEG1) {
        uint2 H, L; split4(x[i], H, L);
        xh[i] = H; xl[i] = L;
    } else if (i < SEG2) {
        int j = i - SEG1;
        float4 v = W_in[j];
        uint2 H; H.x = pack_h2(v.x, v.y); H.y = pack_h2(v.z, v.w);
        Wih[j] = H;
    } else if (i < SEG3) {
        int j = i - SEG2;
        uint2 H, L; split4(W_dt[j], H, L);
        Wdh[j] = H; Wdl[j] = L;
    } else if (i < SEG4) {
        int j = i - SEG3;
        float4 v = W_out[j];
        uint2 H; H.x = pack_h2(v.x, v.y); H.y = pack_h2(v.z, v.w);
        Woh[j] = H;
    } else {
        int j = i - SEG4;               // covers padded [DI x 128] / 4
        int idx = j * 4;
        int r = idx >> 7, c = idx & 127;
        float4 v = (c < 96) ? *(const float4*)(W_x + (size_t)r * 96 + c)
                            : make_float4(0.f, 0.f, 0.f, 0.f);
        uint2 H, L; split4(v, H, L);
        Wxh[j] = H; Wxl[j] = L;
    }
}

// ---------------------------------------------------------------------------
// sum 8 K-split partial slabs -> dbl, + compact fp16 hi/lo of cols 0..63
// ---------------------------------------------------------------------------
__global__ void reduce_dbl_kernel(const float* __restrict__ parts,
                                  float* __restrict__ dbl,
                                  __half* __restrict__ dbh,
                                  __half* __restrict__ dbll)
{
    int i = blockIdx.x * blockDim.x + threadIdx.x;
    if (i >= MROWS * NDP) return;
    float s = 0.f;
#pragma unroll
    for (int k = 0; k < 8; k++) s += parts[(size_t)k * MROWS * NDP + i];
    dbl[i] = s;
    int c = i & 127;
    if (c < 64) {
        int r = i >> 7;
        __half h = __float2half(s);
        dbh [r * DTR + c] = h;
        dbll[r * DTR + c] = __float2half(s - __half2float(h));
    }
}

// sum 2 G4 slabs -> out
__global__ void reduce_out_kernel(const float4* __restrict__ s0,
                                  const float4* __restrict__ s1,
                                  float4* __restrict__ out, int n4)
{
    int i = blockIdx.x * blockDim.x + threadIdx.x;
    if (i >= n4) return;
    float4 a = s0[i], b = s1[i];
    out[i] = make_float4(a.x + b.x, a.y + b.y, a.z + b.z, a.w + b.w);
}

// ---------------------------------------------------------------------------
// Tensor-core GEMM, fp16 split 2/3-term. 128x128 tile, BK=32.
// NS-stage cp.async pipeline (3 for 2-term, 2 for 3-term).
// ---------------------------------------------------------------------------
#define BKT   32
#define AS_ST 40            // A smem row stride (elems): conflict-free, 80B
#define BS_ST 136           // B smem row stride (elems): 272B
#define A_PL  (128*AS_ST)   // 5120 elems
#define B_PL  (32*BS_ST)    // 4352 elems

__device__ __forceinline__ void cp16(uint32_t dst, const void* src) {
    asm volatile("cp.async.cg.shared.global [%0], [%1], 16;\n" :: "r"(dst), "l"(src));
}
__device__ __forceinline__ void ldsm4(uint32_t* r, uint32_t addr) {
    asm volatile("ldmatrix.sync.aligned.m8n8.x4.shared.b16 {%0,%1,%2,%3}, [%4];"
                 : "=r"(r[0]), "=r"(r[1]), "=r"(r[2]), "=r"(r[3]) : "r"(addr));
}
__device__ __forceinline__ void ldsm4t(uint32_t* r, uint32_t addr) {
    asm volatile("ldmatrix.sync.aligned.m8n8.x4.trans.shared.b16 {%0,%1,%2,%3}, [%4];"
                 : "=r"(r[0]), "=r"(r[1]), "=r"(r[2]), "=r"(r[3]) : "r"(addr));
}
__device__ __forceinline__ void mma_f16(float* c, const uint32_t* a, const uint32_t* b) {
    asm volatile("mma.sync.aligned.m16n8k16.row.col.f32.f16.f16.f32 "
                 "{%0,%1,%2,%3},{%4,%5,%6,%7},{%8,%9},{%0,%1,%2,%3};"
                 : "+f"(c[0]), "+f"(c[1]), "+f"(c[2]), "+f"(c[3])
                 : "r"(a[0]), "r"(a[1]), "r"(a[2]), "r"(a[3]), "r"(b[0]), "r"(b[1]));
}

template<bool THREE, int NS>
__global__ __launch_bounds__(256, 2)
void mma_gemm(const __half* __restrict__ Ah, const __half* __restrict__ Al,
              const __half* __restrict__ Bh, const __half* __restrict__ Bl,
              float* __restrict__ C, int Kchunk,
              int lda, int ldb, int ldc,
              size_t slabStride,
              const float* __restrict__ bias)
{
    constexpr int AH_OFF = 0;
    constexpr int AL_OFF = A_PL;
    constexpr int BH_OFF = 2 * A_PL;
    constexpr int BL_OFF = 2 * A_PL + B_PL;
    constexpr uint32_t STAGE_B = (2 * A_PL + (THREE ? 2 : 1) * B_PL) * 2;

    extern __shared__ __align__(16) char dynsmem[];

    const int tid  = threadIdx.x;
    const int lane = tid & 31;
    const int wid  = tid >> 5;
    const int wm   = (wid >> 2) * 64;
    const int wn   = (wid & 3) * 32;
    const int bm   = blockIdx.y * 128;
    const int bn   = blockIdx.x * 128;
    const int kb   = blockIdx.z * Kchunk;

    C += (size_t)blockIdx.z * slabStride;

    const uint32_t sbase = (uint32_t)__cvta_generic_to_shared(dynsmem);

    float acc[4][4][4];
#pragma unroll
    for (int i = 0; i < 4; i++)
#pragma unroll
        for (int j = 0; j < 4; j++)
#pragma unroll
            for (int k = 0; k < 4; k++) acc[i][j][k] = 0.f;

    const int KT = Kchunk >> 5;

    const __half* Ahb = Ah + (size_t)bm * lda + kb;
    const __half* Alb = Al + (size_t)bm * lda + kb;
    const __half* Bhb = Bh + (size_t)kb * ldb + bn;
    const __half* Blb = THREE ? (Bl + (size_t)kb * ldb + bn) : nullptr;

#define ISSUE(stage, kt_) {                                                    \
        uint32_t sb = sbase + (uint32_t)(stage) * STAGE_B;                     \
        int k0 = (kt_) << 5;                                                   \
        _Pragma("unroll")                                                      \
        for (int rep = 0; rep < 2; rep++) {                                    \
            int idx = rep * 256 + tid;                                         \
            int arw = idx >> 2,  acc_ = (idx & 3) * 8;                         \
            int brw = idx >> 4,  bcc_ = (idx & 15) * 8;                        \
            cp16(sb + (AH_OFF + arw * AS_ST + acc_) * 2,                       \
                 Ahb + (size_t)arw * lda + k0 + acc_);                         \
            cp16(sb + (AL_OFF + arw * AS_ST + acc_) * 2,                       \
                 Alb + (size_t)arw * lda + k0 + acc_);                         \
            cp16(sb + (BH_OFF + brw * BS_ST + bcc_) * 2,                       \
                 Bhb + (size_t)(k0 + brw) * ldb + bcc_);                       \
            if (THREE)                                                         \
                cp16(sb + (BL_OFF + brw * BS_ST + bcc_) * 2,                   \
                     Blb + (size_t)(k0 + brw) * ldb + bcc_);                   \
        }                                                                      \
        asm volatile("cp.async.commit_group;\n");                              \
    }

    ISSUE(0, 0);
    if (NS >= 3 && KT > 1) ISSUE(1, 1);

    const int arow = lane & 15;
    const int acol = (lane >> 4) * 8;

    for (int kt = 0; kt < KT; ++kt) {
        if (NS >= 3 && kt + 1 < KT) asm volatile("cp.async.wait_group 1;\n");
        else                        asm volatile("cp.async.wait_group 0;\n");
        __syncthreads();

        if (NS >= 3) { if (kt + 2 < KT) ISSUE((kt + 2) % NS, kt + 2); }
        else         { if (kt + 1 < KT) ISSUE((kt + 1) & 1,  kt + 1); }

        uint32_t sb = sbase + (uint32_t)(kt % NS) * STAGE_B;

#pragma unroll
        for (int ks = 0; ks < 2; ks++) {
            const int kso = ks * 16;
            uint32_t ah[4][4], al[4][4], bx[4][2];
#pragma unroll
            for (int i = 0; i < 4; i++)
                ldsm4(ah[i], sb + (uint32_t)(AH_OFF + (wm + i * 16 + arow) * AS_ST + kso + acol) * 2);
#pragma unroll
            for (int jj = 0; jj < 2; jj++) {
                uint32_t r[4];
                ldsm4t(r, sb + (uint32_t)(BH_OFF + (kso + arow) * BS_ST + wn + jj * 16 + acol) * 2);
                bx[2 * jj][0] = r[0]; bx[2 * jj][1] = r[1];
                bx[2 * jj + 1][0] = r[2]; bx[2 * jj + 1][1] = r[3];
            }
#pragma unroll
            for (int i = 0; i < 4; i++)
#pragma unroll
                for (int j = 0; j < 4; j++) mma_f16(acc[i][j], ah[i], bx[j]);

#pragma unroll
            for (int i = 0; i < 4; i++)
                ldsm4(al[i], sb + (uint32_t)(AL_OFF + (wm + i * 16 + arow) * AS_ST + kso + acol) * 2);
#pragma unroll
            for (int i = 0; i < 4; i++)
#pragma unroll
                for (int j = 0; j < 4; j++) mma_f16(acc[i][j], al[i], bx[j]);

            if (THREE) {
#pragma unroll
                for (int jj = 0; jj < 2; jj++) {
                    uint32_t r[4];
                    ldsm4t(r, sb + (uint32_t)(BL_OFF + (kso + arow) * BS_ST + wn + jj * 16 + acol) * 2);
                    bx[2 * jj][0] = r[0]; bx[2 * jj][1] = r[1];
                    bx[2 * jj + 1][0] = r[2]; bx[2 * jj + 1][1] = r[3];
                }
#pragma unroll
                for (int i = 0; i < 4; i++)
#pragma unroll
                    for (int j = 0; j < 4; j++) mma_f16(acc[i][j], ah[i], bx[j]);
            }
        }
    }
#undef ISSUE

    const bool sp = (bias != nullptr);
#pragma unroll
    for (int i = 0; i < 4; i++) {
        int row0 = bm + wm + i * 16 + (lane >> 2);
#pragma unroll
        for (int j = 0; j < 4; j++) {
            int col = bn + wn + j * 8 + (lane & 3) * 2;
            float v0 = acc[i][j][0], v1 = acc[i][j][1];
            float v2 = acc[i][j][2], v3 = acc[i][j][3];
            if (sp) {
                float b0 = bias[col], b1 = bias[col + 1];
                v0 += b0; v1 += b1; v2 += b0; v3 += b1;
                v0 = (v0 > 20.f) ? v0 : log1pf(__expf(v0));
                v1 = (v1 > 20.f) ? v1 : log1pf(__expf(v1));
                v2 = (v2 > 20.f) ? v2 : log1pf(__expf(v2));
                v3 = (v3 > 20.f) ? v3 : log1pf(__expf(v3));
            }
            *(float2*)(C + (size_t)row0 * ldc + col)       = make_float2(v0, v1);
            *(float2*)(C + (size_t)(row0 + 8) * ldc + col) = make_float2(v2, v3);
        }
    }
}

// ---------------------------------------------------------------------------
// Depthwise causal conv (width 4) + bias + SiLU; emits fp32 + fp16 hi/lo.
// ---------------------------------------------------------------------------
__global__ void conv_silu_kernel(const float* __restrict__ xz,
                                 const float* __restrict__ conv_w,
                                 const float* __restrict__ conv_b,
                                 float* __restrict__ xc,
                                 __half* __restrict__ xch,
                                 __half* __restrict__ xcl)
{
    int idx = blockIdx.x * blockDim.x + threadIdx.x;
    if (idx >= MROWS * DI) return;
    int d = idx & (DI - 1);
    int l = (idx >> 11) & (LC - 1);
    int b = idx >> 21;

    float acc = conv_b[d];
#pragma unroll
    for (int j = 0; j < DCNV; j++) {
        int ll = l + j - (DCNV - 1);
        if (ll >= 0)
            acc += xz[(size_t)(b * LC + ll) * NXZ + d] * conv_w[d * DCNV + j];
    }
    float v = acc / (1.f + __expf(-acc));
    xc[idx] = v;
    __half h = __float2half(v);
    xch[idx] = h;
    xcl[idx] = __float2half(v - __half2float(h));
}

// ---------------------------------------------------------------------------
// Selective scan: 8 lanes/channel, 2 states/lane, chunk-4 double buffering.
// ---------------------------------------------------------------------------
#define SCH 4
__global__ __launch_bounds__(256)
void scan_kernel(const float* __restrict__ dt,
                 const float* __restrict__ xc,
                 const float* __restrict__ dbl,
                 const float* __restrict__ xz,
                 const float* __restrict__ A_log,
                 const float* __restrict__ D_par,
                 __half* __restrict__ yh,
                 __half* __restrict__ yl)
{
    const int gtid = blockIdx.x * 256 + threadIdx.x;
    const int ch = gtid >> 3;
    const int nl = gtid & 7;
    const int n0 = nl * 2;
    const int b  = ch >> 11;
    const int d  = ch & (DI - 1);

    const float An0 = -expf(A_log[d * DS + n0]);
    const float An1 = -expf(A_log[d * DS + n0 + 1]);
    const float Dv  = D_par[d];
    float h0 = 0.f, h1 = 0.f;

    const size_t rowbase = (size_t)b * LC;
    const float* pdt = dt  + rowbase * DI + d;
    const float* pxc = xc  + rowbase * DI + d;
    const float* pBC = dbl + rowbase * NDP + 64 + n0;
    const float* pz  = xz  + rowbase * NXZ + DI + d;
    __half* pyh = yh + rowbase * DI + d;
    __half* pyl = yl + rowbase * DI + d;

    float  dtb_[2][SCH], xcb[2][SCH], zb[2][SCH];
    float2 Bb[2][SCH], Cb[2][SCH];

#define LOADG(g_, p_) {                                                        \
        _Pragma("unroll")                                                      \
        for (int u = 0; u < SCH; u++) {                                        \
            size_t row = (size_t)((g_) * SCH + u);                             \
            dtb_[p_][u] = __ldg(pdt + row * DI);                               \
            xcb[p_][u]  = __ldg(pxc + row * DI);                               \
            Bb[p_][u]   = __ldg((const float2*)(pBC + row * NDP));             \
            Cb[p_][u]   = __ldg((const float2*)(pBC + row * NDP + DS));        \
            zb[p_][u]   = (nl == 0) ? __ldg(pz + row * NXZ) : 0.f;             \
        }                                                                      \
    }

    const int NG = LC / SCH;
    LOADG(0, 0);

#pragma unroll 2
    for (int g = 0; g < NG; g++) {
        const int p = g & 1;
        if (g + 1 < NG) LOADG(g + 1, p ^ 1);

#pragma unroll
        for (int u = 0; u < SCH; u++) {
            float dtv = dtb_[p][u], xcv = xcb[p][u];
            float2 Bv = Bb[p][u],   Cv  = Cb[p][u];

            float dx = dtv * xcv;
            h0 = __expf(dtv * An0) * h0 + dx * Bv.x;
            h1 = __expf(dtv * An1) * h1 + dx * Bv.y;

            float yv = h0 * Cv.x + h1 * Cv.y;
            yv += __shfl_xor_sync(0xffffffffu, yv, 4);
            yv += __shfl_xor_sync(0xffffffffu, yv, 2);
            yv += __shfl_xor_sync(0xffffffffu, yv, 1);

            if (nl == 0) {
                float zv  = zb[p][u];
                float sil = zv / (1.f + __expf(-zv));
                float yo  = (yv + xcv * Dv) * sil;
                size_t row = (size_t)(g * SCH + u);
                __half hh = __float2half(yo);
                pyh[row * DI] = hh;
                pyl[row * DI] = __float2half(yo - __half2float(hh));
            }
        }
    }
#undef LOADG
}

// ---------------------------------------------------------------------------
extern "C" void kernel_launch(void* const* d_in, const int* in_sizes, int n_in,
                              void* d_out, int out_size)
{
    const float* x      = (const float*)d_in[0];
    const float* W_in   = (const float*)d_in[1];
    const float* conv_w = (const float*)d_in[2];
    const float* conv_b = (const float*)d_in[3];
    const float* W_x    = (const float*)d_in[4];
    const float* W_dt   = (const float*)d_in[5];
    const float* b_dt   = (const float*)d_in[6];
    const float* A_log  = (const float*)d_in[7];
    const float* D_par  = (const float*)d_in[8];
    const float* W_out  = (const float*)d_in[9];
    float* out = (float*)d_out;

    float *xz, *xc, *dtb, *dbl, *dblp, *osp;
    __half *xh, *xl, *Wih, *Wxh, *Wxl, *xch, *xcl,
           *dbh, *dbll, *Wdh, *Wdl, *yh, *yl, *Woh;
    cudaGetSymbolAddress((void**)&xz,   g_xz);
    cudaGetSymbolAddress((void**)&xc,   g_xc);
    cudaGetSymbolAddress((void**)&dtb,  g_dt);
    cudaGetSymbolAddress((void**)&dbl,  g_dbl);
    cudaGetSymbolAddress((void**)&dblp, g_dblp);
    cudaGetSymbolAddress((void**)&osp,  g_osp);
    cudaGetSymbolAddress((void**)&xh,   g_xh);   cudaGetSymbolAddress((void**)&xl,   g_xl);
    cudaGetSymbolAddress((void**)&Wih,  g_Wih);
    cudaGetSymbolAddress((void**)&Wxh,  g_Wxh);  cudaGetSymbolAddress((void**)&Wxl,  g_Wxl);
    cudaGetSymbolAddress((void**)&xch,  g_xch);  cudaGetSymbolAddress((void**)&xcl,  g_xcl);
    cudaGetSymbolAddress((void**)&dbh,  g_dbh);  cudaGetSymbolAddress((void**)&dbll, g_dbll);
    cudaGetSymbolAddress((void**)&Wdh,  g_Wdh);  cudaGetSymbolAddress((void**)&Wdl,  g_Wdl);
    cudaGetSymbolAddress((void**)&yh,   g_yh);   cudaGetSymbolAddress((void**)&yl,   g_yl);
    cudaGetSymbolAddress((void**)&Woh,  g_Woh);

    const int SMEM2 = 3 * (2 * A_PL + 1 * B_PL) * 2;   // 87552
    const int SMEM3 = 2 * (2 * A_PL + 2 * B_PL) * 2;   // 75776
    cudaFuncSetAttribute((const void*)mma_gemm<false, 3>,
                         cudaFuncAttributeMaxDynamicSharedMemorySize, SMEM2);
    cudaFuncSetAttribute((const void*)mma_gemm<true, 2>,
                         cudaFuncAttributeMaxDynamicSharedMemorySize, SMEM3);

    // 0) all input conversions in one kernel
    prep_kernel<<<(SEG5 + 255) / 256, 256>>>(
        (const float4*)x, (const float4*)W_in, (const float4*)W_dt,
        (const float4*)W_out, W_x,
        (uint2*)xh, (uint2*)xl, (uint2*)Wih,
        (uint2*)Wdh, (uint2*)Wdl, (uint2*)Woh, (uint2*)Wxh, (uint2*)Wxl);

    // 1) xz = x @ W_in (2-term, NS=3)
    mma_gemm<false, 3><<<dim3(NXZ / 128, MROWS / 128, 1), 256, SMEM2>>>(
        xh, xl, Wih, nullptr, xz, DM, DM, NXZ, NXZ, 0, nullptr);

    // 2) conv + SiLU (+ fp16 split)
    conv_silu_kernel<<<(MROWS * DI) / 256, 256>>>(xz, conv_w, conv_b, xc, xch, xcl);

    // 3) dbl = xc @ W_x_padded (3-term), K-split 8
    mma_gemm<true, 2><<<dim3(1, MROWS / 128, 8), 256, SMEM3>>>(
        xch, xcl, Wxh, Wxl, dblp, DI / 8, DI, NDP, NDP,
        (size_t)MROWS * NDP, nullptr);

    // 4) reduce partials + compact fp16 of dt-rank slice
    reduce_dbl_kernel<<<(MROWS * NDP + 255) / 256, 256>>>(dblp, dbl, dbh, dbll);

    // 5) dt = softplus(dbl[:,:64] @ W_dt + b_dt) (3-term)
    mma_gemm<true, 2><<<dim3(DI / 128, MROWS / 128, 1), 256, SMEM3>>>(
        dbh, dbll, Wdh, Wdl, dtb, DTR, DTR, DI, DI, 0, b_dt);

    // 6) selective scan -> y (fp16 hi/lo)
    scan_kernel<<<(BC * DI * 8) / 256, 256>>>(dtb, xc, dbl, xz, A_log, D_par, yh, yl);

    // 7) out = y @ W_out (2-term), K-split 2 -> slabs
    mma_gemm<false, 3><<<dim3(DM / 128, MROWS / 128, 2), 256, SMEM2>>>(
        yh, yl, Woh, nullptr, osp, DI / 2, DI, DM, DM,
        (size_t)MROWS * DM, nullptr);

    // 8) out = slab0 + slab1
    reduce_out_kernel<<<(MROWS * DM / 4 + 255) / 256, 256>>>(
        (const float4*)osp, (const float4*)(osp + (size_t)MROWS * DM),
        (float4*)out, MROWS * DM / 4);
}

// round 8
// speedup vs baseline: 4.8317x; 1.1235x over previous
#include <cuda_runtime.h>
#include <cuda_fp16.h>
#include <cstdint>

// Problem dims (fixed)
#define BC   2
#define LC   1024
#define DM   1024
#define DI   2048
#define DS   16
#define DCNV 4
#define DTR  64
#define MROWS (BC*LC)      // 2048
#define NXZ   (2*DI)       // 4096
#define NDP   128

// ---------------- scratch (device globals) ----------------
__device__ float g_xz  [MROWS * NXZ];
__device__ float g_xc  [MROWS * DI];
__device__ float g_dt  [MROWS * DI];
__device__ float g_dbl [MROWS * NDP];
__device__ float g_dblp[8 * MROWS * NDP];
__device__ float g_osp [2 * MROWS * DM];     // G4 split-K slabs

__device__ __half g_xh  [MROWS * DM];
__device__ __half g_Wih [DM * NXZ];
__device__ __half g_Wxh [DI * NDP],    g_Wxl [DI * NDP];
__device__ __half g_xch [MROWS * DI],  g_xcl [MROWS * DI];
__device__ __half g_dbh [MROWS * DTR], g_dbll[MROWS * DTR];
__device__ __half g_Wdh [DTR * DI],    g_Wdl [DTR * DI];
__device__ __half g_yh  [MROWS * DI],  g_yl  [MROWS * DI];
__device__ __half g_Woh [DI * DM];

// ---------------------------------------------------------------------------
// helpers
// ---------------------------------------------------------------------------
__device__ __forceinline__ uint32_t pack_h2(float a, float b) {
    __half2 h = __floats2half2_rn(a, b);
    return *reinterpret_cast<uint32_t*>(&h);
}
__device__ __forceinline__ void split4(float4 v, uint2& H, uint2& L) {
    float hx = __half2float(__float2half(v.x));
    float hy = __half2float(__float2half(v.y));
    float hz = __half2float(__float2half(v.z));
    float hw = __half2float(__float2half(v.w));
    H.x = pack_h2(v.x, v.y);            H.y = pack_h2(v.z, v.w);
    L.x = pack_h2(v.x - hx, v.y - hy);  L.y = pack_h2(v.z - hz, v.w - hw);
}

// ---------------------------------------------------------------------------
// Fused conversion. Unit = 4 fp32 elements. Segments (float4 units):
//   [0,SEG1): x -> xh (hi only)        [SEG1,SEG2): W_in -> Wih (hi)
//   [SEG2,SEG3): W_dt -> hi/lo         [SEG3,SEG4): W_out -> Woh (hi)
//   [SEG4,SEG5): W_x -> hi/lo padded [DI x 128]
// ---------------------------------------------------------------------------
#define SEG1  524288
#define SEG2 1572864
#define SEG3 1605632
#define SEG4 2129920
#define SEG5 2195456

__global__ void prep_kernel(const float4* __restrict__ x,
                            const float4* __restrict__ W_in,
                            const float4* __restrict__ W_dt,
                            const float4* __restrict__ W_out,
                            const float*  __restrict__ W_x,
                            uint2* __restrict__ xh,
                            uint2* __restrict__ Wih,
                            uint2* __restrict__ Wdh, uint2* __restrict__ Wdl,
                            uint2* __restrict__ Woh,
                            uint2* __restrict__ Wxh, uint2* __restrict__ Wxl)
{
    int i = blockIdx.x * blockDim.x + threadIdx.x;
    if (i >= SEG5) return;
    if (i < SEG1) {
        float4 v = x[i];
        uint2 H; H.x = pack_h2(v.x, v.y); H.y = pack_h2(v.z, v.w);
        xh[i] = H;
    } else if (i < SEG2) {
        int j = i - SEG1;
        float4 v = W_in[j];
        uint2 H; H.x = pack_h2(v.x, v.y); H.y = pack_h2(v.z, v.w);
        Wih[j] = H;
    } else if (i < SEG3) {
        int j = i - SEG2;
        uint2 H, L; split4(W_dt[j], H, L);
        Wdh[j] = H; Wdl[j] = L;
    } else if (i < SEG4) {
        int j = i - SEG3;
        float4 v = W_out[j];
        uint2 H; H.x = pack_h2(v.x, v.y); H.y = pack_h2(v.z, v.w);
        Woh[j] = H;
    } else {
        int j = i - SEG4;
        int idx = j * 4;
        int r = idx >> 7, c = idx & 127;
        float4 v = (c < 96) ? *(const float4*)(W_x + (size_t)r * 96 + c)
                            : make_float4(0.f, 0.f, 0.f, 0.f);
        uint2 H, L; split4(v, H, L);
        Wxh[j] = H; Wxl[j] = L;
    }
}

// ---------------------------------------------------------------------------
// reduces
// ---------------------------------------------------------------------------
__global__ void reduce_dbl_kernel(const float* __restrict__ parts,
                                  float* __restrict__ dbl,
                                  __half* __restrict__ dbh,
                                  __half* __restrict__ dbll)
{
    int i = blockIdx.x * blockDim.x + threadIdx.x;
    if (i >= MROWS * NDP) return;
    float s = 0.f;
#pragma unroll
    for (int k = 0; k < 8; k++) s += parts[(size_t)k * MROWS * NDP + i];
    dbl[i] = s;
    int c = i & 127;
    if (c < 64) {
        int r = i >> 7;
        __half h = __float2half(s);
        dbh [r * DTR + c] = h;
        dbll[r * DTR + c] = __float2half(s - __half2float(h));
    }
}

__global__ void reduce_out_kernel(const float4* __restrict__ s0,
                                  const float4* __restrict__ s1,
                                  float4* __restrict__ out, int n4)
{
    int i = blockIdx.x * blockDim.x + threadIdx.x;
    if (i >= n4) return;
    float4 a = s0[i], b = s1[i];
    out[i] = make_float4(a.x + b.x, a.y + b.y, a.z + b.z, a.w + b.w);
}

// ---------------------------------------------------------------------------
// Tensor-core GEMM, fp16, TERMS = 1 (AhBh), 2 (+AlBh), 3 (+AhBl).
// 128x128 tile, BK=32, NS-stage cp.async pipeline.
// ---------------------------------------------------------------------------
#define AS_ST 40
#define BS_ST 136
#define A_PL  (128*AS_ST)   // 5120 elems
#define B_PL  (32*BS_ST)    // 4352 elems

__device__ __forceinline__ void cp16(uint32_t dst, const void* src) {
    asm volatile("cp.async.cg.shared.global [%0], [%1], 16;\n" :: "r"(dst), "l"(src));
}
__device__ __forceinline__ void ldsm4(uint32_t* r, uint32_t addr) {
    asm volatile("ldmatrix.sync.aligned.m8n8.x4.shared.b16 {%0,%1,%2,%3}, [%4];"
                 : "=r"(r[0]), "=r"(r[1]), "=r"(r[2]), "=r"(r[3]) : "r"(addr));
}
__device__ __forceinline__ void ldsm4t(uint32_t* r, uint32_t addr) {
    asm volatile("ldmatrix.sync.aligned.m8n8.x4.trans.shared.b16 {%0,%1,%2,%3}, [%4];"
                 : "=r"(r[0]), "=r"(r[1]), "=r"(r[2]), "=r"(r[3]) : "r"(addr));
}
__device__ __forceinline__ void mma_f16(float* c, const uint32_t* a, const uint32_t* b) {
    asm volatile("mma.sync.aligned.m16n8k16.row.col.f32.f16.f16.f32 "
                 "{%0,%1,%2,%3},{%4,%5,%6,%7},{%8,%9},{%0,%1,%2,%3};"
                 : "+f"(c[0]), "+f"(c[1]), "+f"(c[2]), "+f"(c[3])
                 : "r"(a[0]), "r"(a[1]), "r"(a[2]), "r"(a[3]), "r"(b[0]), "r"(b[1]));
}

template<int TERMS, int NS>
__global__ __launch_bounds__(256, 2)
void mma_gemm(const __half* __restrict__ Ah, const __half* __restrict__ Al,
              const __half* __restrict__ Bh, const __half* __restrict__ Bl,
              float* __restrict__ C, int Kchunk,
              int lda, int ldb, int ldc,
              size_t slabStride,
              const float* __restrict__ bias)
{
    constexpr int NA = (TERMS >= 2) ? 2 : 1;
    constexpr int NB = (TERMS >= 3) ? 2 : 1;
    constexpr int AH_OFF = 0;
    constexpr int AL_OFF = A_PL;                // valid iff NA==2
    constexpr int BH_OFF = NA * A_PL;
    constexpr int BL_OFF = NA * A_PL + B_PL;    // valid iff NB==2
    constexpr uint32_t STAGE_B = (NA * A_PL + NB * B_PL) * 2;

    extern __shared__ __align__(16) char dynsmem[];

    const int tid  = threadIdx.x;
    const int lane = tid & 31;
    const int wid  = tid >> 5;
    const int wm   = (wid >> 2) * 64;
    const int wn   = (wid & 3) * 32;
    const int bm   = blockIdx.y * 128;
    const int bn   = blockIdx.x * 128;
    const int kb   = blockIdx.z * Kchunk;

    C += (size_t)blockIdx.z * slabStride;

    const uint32_t sbase = (uint32_t)__cvta_generic_to_shared(dynsmem);

    float acc[4][4][4];
#pragma unroll
    for (int i = 0; i < 4; i++)
#pragma unroll
        for (int j = 0; j < 4; j++)
#pragma unroll
            for (int k = 0; k < 4; k++) acc[i][j][k] = 0.f;

    const int KT = Kchunk >> 5;

    const __half* Ahb = Ah + (size_t)bm * lda + kb;
    const __half* Alb = (TERMS >= 2) ? (Al + (size_t)bm * lda + kb) : nullptr;
    const __half* Bhb = Bh + (size_t)kb * ldb + bn;
    const __half* Blb = (TERMS >= 3) ? (Bl + (size_t)kb * ldb + bn) : nullptr;

#define ISSUE(stage, kt_) {                                                    \
        uint32_t sb = sbase + (uint32_t)(stage) * STAGE_B;                     \
        int k0 = (kt_) << 5;                                                   \
        _Pragma("unroll")                                                      \
        for (int rep = 0; rep < 2; rep++) {                                    \
            int idx = rep * 256 + tid;                                         \
            int arw = idx >> 2,  acc_ = (idx & 3) * 8;                         \
            int brw = idx >> 4,  bcc_ = (idx & 15) * 8;                        \
            cp16(sb + (AH_OFF + arw * AS_ST + acc_) * 2,                       \
                 Ahb + (size_t)arw * lda + k0 + acc_);                         \
            if (TERMS >= 2)                                                    \
                cp16(sb + (AL_OFF + arw * AS_ST + acc_) * 2,                   \
                     Alb + (size_t)arw * lda + k0 + acc_);                     \
            cp16(sb + (BH_OFF + brw * BS_ST + bcc_) * 2,                       \
                 Bhb + (size_t)(k0 + brw) * ldb + bcc_);                       \
            if (TERMS >= 3)                                                    \
                cp16(sb + (BL_OFF + brw * BS_ST + bcc_) * 2,                   \
                     Blb + (size_t)(k0 + brw) * ldb + bcc_);                   \
        }                                                                      \
        asm volatile("cp.async.commit_group;\n");                              \
    }

    ISSUE(0, 0);
    if (NS >= 3 && KT > 1) ISSUE(1, 1);

    const int arow = lane & 15;
    const int acol = (lane >> 4) * 8;

    for (int kt = 0; kt < KT; ++kt) {
        if (NS >= 3 && kt + 1 < KT) asm volatile("cp.async.wait_group 1;\n");
        else                        asm volatile("cp.async.wait_group 0;\n");
        __syncthreads();

        if (NS >= 3) { if (kt + 2 < KT) ISSUE((kt + 2) % NS, kt + 2); }
        else         { if (kt + 1 < KT) ISSUE((kt + 1) & 1,  kt + 1); }

        uint32_t sb = sbase + (uint32_t)(kt % NS) * STAGE_B;

#pragma unroll
        for (int ks = 0; ks < 2; ks++) {
            const int kso = ks * 16;
            uint32_t ah[4][4], bx[4][2];
#pragma unroll
            for (int i = 0; i < 4; i++)
                ldsm4(ah[i], sb + (uint32_t)(AH_OFF + (wm + i * 16 + arow) * AS_ST + kso + acol) * 2);
#pragma unroll
            for (int jj = 0; jj < 2; jj++) {
                uint32_t r[4];
                ldsm4t(r, sb + (uint32_t)(BH_OFF + (kso + arow) * BS_ST + wn + jj * 16 + acol) * 2);
                bx[2 * jj][0] = r[0]; bx[2 * jj][1] = r[1];
                bx[2 * jj + 1][0] = r[2]; bx[2 * jj + 1][1] = r[3];
            }
#pragma unroll
            for (int i = 0; i < 4; i++)
#pragma unroll
                for (int j = 0; j < 4; j++) mma_f16(acc[i][j], ah[i], bx[j]);

            if (TERMS >= 2) {
                uint32_t al[4][4];
#pragma unroll
                for (int i = 0; i < 4; i++)
                    ldsm4(al[i], sb + (uint32_t)(AL_OFF + (wm + i * 16 + arow) * AS_ST + kso + acol) * 2);
#pragma unroll
                for (int i = 0; i < 4; i++)
#pragma unroll
                    for (int j = 0; j < 4; j++) mma_f16(acc[i][j], al[i], bx[j]);
            }
            if (TERMS >= 3) {
#pragma unroll
                for (int jj = 0; jj < 2; jj++) {
                    uint32_t r[4];
                    ldsm4t(r, sb + (uint32_t)(BL_OFF + (kso + arow) * BS_ST + wn + jj * 16 + acol) * 2);
                    bx[2 * jj][0] = r[0]; bx[2 * jj][1] = r[1];
                    bx[2 * jj + 1][0] = r[2]; bx[2 * jj + 1][1] = r[3];
                }
#pragma unroll
                for (int i = 0; i < 4; i++)
#pragma unroll
                    for (int j = 0; j < 4; j++) mma_f16(acc[i][j], ah[i], bx[j]);
            }
        }
    }
#undef ISSUE

    const bool sp = (bias != nullptr);
#pragma unroll
    for (int i = 0; i < 4; i++) {
        int row0 = bm + wm + i * 16 + (lane >> 2);
#pragma unroll
        for (int j = 0; j < 4; j++) {
            int col = bn + wn + j * 8 + (lane & 3) * 2;
            float v0 = acc[i][j][0], v1 = acc[i][j][1];
            float v2 = acc[i][j][2], v3 = acc[i][j][3];
            if (sp) {
                float b0 = bias[col], b1 = bias[col + 1];
                v0 += b0; v1 += b1; v2 += b0; v3 += b1;
                v0 = (v0 > 20.f) ? v0 : log1pf(__expf(v0));
                v1 = (v1 > 20.f) ? v1 : log1pf(__expf(v1));
                v2 = (v2 > 20.f) ? v2 : log1pf(__expf(v2));
                v3 = (v3 > 20.f) ? v3 : log1pf(__expf(v3));
            }
            *(float2*)(C + (size_t)row0 * ldc + col)       = make_float2(v0, v1);
            *(float2*)(C + (size_t)(row0 + 8) * ldc + col) = make_float2(v2, v3);
        }
    }
}

// ---------------------------------------------------------------------------
// Depthwise causal conv (width 4) + bias + SiLU; emits fp32 + fp16 hi/lo.
// ---------------------------------------------------------------------------
__global__ void conv_silu_kernel(const float* __restrict__ xz,
                                 const float* __restrict__ conv_w,
                                 const float* __restrict__ conv_b,
                                 float* __restrict__ xc,
                                 __half* __restrict__ xch,
                                 __half* __restrict__ xcl)
{
    int idx = blockIdx.x * blockDim.x + threadIdx.x;
    if (idx >= MROWS * DI) return;
    int d = idx & (DI - 1);
    int l = (idx >> 11) & (LC - 1);
    int b = idx >> 21;

    float acc = conv_b[d];
#pragma unroll
    for (int j = 0; j < DCNV; j++) {
        int ll = l + j - (DCNV - 1);
        if (ll >= 0)
            acc += xz[(size_t)(b * LC + ll) * NXZ + d] * conv_w[d * DCNV + j];
    }
    float v = acc / (1.f + __expf(-acc));
    xc[idx] = v;
    __half h = __float2half(v);
    xch[idx] = h;
    xcl[idx] = __float2half(v - __half2float(h));
}

// ---------------------------------------------------------------------------
// Selective scan: 8 lanes/channel, 2 states/lane, chunk-4 double buffering.
// ---------------------------------------------------------------------------
#define SCH 4
__global__ __launch_bounds__(256)
void scan_kernel(const float* __restrict__ dt,
                 const float* __restrict__ xc,
                 const float* __restrict__ dbl,
                 const float* __restrict__ xz,
                 const float* __restrict__ A_log,
                 const float* __restrict__ D_par,
                 __half* __restrict__ yh,
                 __half* __restrict__ yl)
{
    const int gtid = blockIdx.x * 256 + threadIdx.x;
    const int ch = gtid >> 3;
    const int nl = gtid & 7;
    const int n0 = nl * 2;
    const int b  = ch >> 11;
    const int d  = ch & (DI - 1);

    const float An0 = -expf(A_log[d * DS + n0]);
    const float An1 = -expf(A_log[d * DS + n0 + 1]);
    const float Dv  = D_par[d];
    float h0 = 0.f, h1 = 0.f;

    const size_t rowbase = (size_t)b * LC;
    const float* pdt = dt  + rowbase * DI + d;
    const float* pxc = xc  + rowbase * DI + d;
    const float* pBC = dbl + rowbase * NDP + 64 + n0;
    const float* pz  = xz  + rowbase * NXZ + DI + d;
    __half* pyh = yh + rowbase * DI + d;
    __half* pyl = yl + rowbase * DI + d;

    float  dtb_[2][SCH], xcb[2][SCH], zb[2][SCH];
    float2 Bb[2][SCH], Cb[2][SCH];

#define LOADG(g_, p_) {                                                        \
        _Pragma("unroll")                                                      \
        for (int u = 0; u < SCH; u++) {                                        \
            size_t row = (size_t)((g_) * SCH + u);                             \
            dtb_[p_][u] = __ldg(pdt + row * DI);                               \
            xcb[p_][u]  = __ldg(pxc + row * DI);                               \
            Bb[p_][u]   = __ldg((const float2*)(pBC + row * NDP));             \
            Cb[p_][u]   = __ldg((const float2*)(pBC + row * NDP + DS));        \
            zb[p_][u]   = (nl == 0) ? __ldg(pz + row * NXZ) : 0.f;             \
        }                                                                      \
    }

    const int NG = LC / SCH;
    LOADG(0, 0);

#pragma unroll 2
    for (int g = 0; g < NG; g++) {
        const int p = g & 1;
        if (g + 1 < NG) LOADG(g + 1, p ^ 1);

#pragma unroll
        for (int u = 0; u < SCH; u++) {
            float dtv = dtb_[p][u], xcv = xcb[p][u];
            float2 Bv = Bb[p][u],   Cv  = Cb[p][u];

            float dx = dtv * xcv;
            h0 = __expf(dtv * An0) * h0 + dx * Bv.x;
            h1 = __expf(dtv * An1) * h1 + dx * Bv.y;

            float yv = h0 * Cv.x + h1 * Cv.y;
            yv += __shfl_xor_sync(0xffffffffu, yv, 4);
            yv += __shfl_xor_sync(0xffffffffu, yv, 2);
            yv += __shfl_xor_sync(0xffffffffu, yv, 1);

            if (nl == 0) {
                float zv  = zb[p][u];
                float sil = zv / (1.f + __expf(-zv));
                float yo  = (yv + xcv * Dv) * sil;
                size_t row = (size_t)(g * SCH + u);
                __half hh = __float2half(yo);
                pyh[row * DI] = hh;
                pyl[row * DI] = __float2half(yo - __half2float(hh));
            }
        }
    }
#undef LOADG
}

// ---------------------------------------------------------------------------
extern "C" void kernel_launch(void* const* d_in, const int* in_sizes, int n_in,
                              void* d_out, int out_size)
{
    const float* x      = (const float*)d_in[0];
    const float* W_in   = (const float*)d_in[1];
    const float* conv_w = (const float*)d_in[2];
    const float* conv_b = (const float*)d_in[3];
    const float* W_x    = (const float*)d_in[4];
    const float* W_dt   = (const float*)d_in[5];
    const float* b_dt   = (const float*)d_in[6];
    const float* A_log  = (const float*)d_in[7];
    const float* D_par  = (const float*)d_in[8];
    const float* W_out  = (const float*)d_in[9];
    float* out = (float*)d_out;

    float *xz, *xc, *dtb, *dbl, *dblp, *osp;
    __half *xh, *Wih, *Wxh, *Wxl, *xch, *xcl,
           *dbh, *dbll, *Wdh, *Wdl, *yh, *yl, *Woh;
    cudaGetSymbolAddress((void**)&xz,   g_xz);
    cudaGetSymbolAddress((void**)&xc,   g_xc);
    cudaGetSymbolAddress((void**)&dtb,  g_dt);
    cudaGetSymbolAddress((void**)&dbl,  g_dbl);
    cudaGetSymbolAddress((void**)&dblp, g_dblp);
    cudaGetSymbolAddress((void**)&osp,  g_osp);
    cudaGetSymbolAddress((void**)&xh,   g_xh);
    cudaGetSymbolAddress((void**)&Wih,  g_Wih);
    cudaGetSymbolAddress((void**)&Wxh,  g_Wxh);  cudaGetSymbolAddress((void**)&Wxl,  g_Wxl);
    cudaGetSymbolAddress((void**)&xch,  g_xch);  cudaGetSymbolAddress((void**)&xcl,  g_xcl);
    cudaGetSymbolAddress((void**)&dbh,  g_dbh);  cudaGetSymbolAddress((void**)&dbll, g_dbll);
    cudaGetSymbolAddress((void**)&Wdh,  g_Wdh);  cudaGetSymbolAddress((void**)&Wdl,  g_Wdl);
    cudaGetSymbolAddress((void**)&yh,   g_yh);   cudaGetSymbolAddress((void**)&yl,   g_yl);
    cudaGetSymbolAddress((void**)&Woh,  g_Woh);

    const int SMEM1 = 3 * (1 * A_PL + 1 * B_PL) * 2;   // 56832
    const int SMEM2 = 3 * (2 * A_PL + 1 * B_PL) * 2;   // 87552
    const int SMEM3 = 2 * (2 * A_PL + 2 * B_PL) * 2;   // 75776
    cudaFuncSetAttribute((const void*)mma_gemm<1, 3>,
                         cudaFuncAttributeMaxDynamicSharedMemorySize, SMEM1);
    cudaFuncSetAttribute((const void*)mma_gemm<2, 3>,
                         cudaFuncAttributeMaxDynamicSharedMemorySize, SMEM2);
    cudaFuncSetAttribute((const void*)mma_gemm<3, 2>,
                         cudaFuncAttributeMaxDynamicSharedMemorySize, SMEM3);

    // 0) all input conversions in one kernel
    prep_kernel<<<(SEG5 + 255) / 256, 256>>>(
        (const float4*)x, (const float4*)W_in, (const float4*)W_dt,
        (const float4*)W_out, W_x,
        (uint2*)xh, (uint2*)Wih,
        (uint2*)Wdh, (uint2*)Wdl, (uint2*)Woh, (uint2*)Wxh, (uint2*)Wxl);

    // 1) xz = x @ W_in (1-term)
    mma_gemm<1, 3><<<dim3(NXZ / 128, MROWS / 128, 1), 256, SMEM1>>>(
        xh, nullptr, Wih, nullptr, xz, DM, DM, NXZ, NXZ, 0, nullptr);

    // 2) conv + SiLU (+ fp16 split)
    conv_silu_kernel<<<(MROWS * DI) / 256, 256>>>(xz, conv_w, conv_b, xc, xch, xcl);

    // 3) dbl = xc @ W_x_padded (3-term), K-split 8
    mma_gemm<3, 2><<<dim3(1, MROWS / 128, 8), 256, SMEM3>>>(
        xch, xcl, Wxh, Wxl, dblp, DI / 8, DI, NDP, NDP,
        (size_t)MROWS * NDP, nullptr);

    // 4) reduce partials + compact fp16 of dt-rank slice
    reduce_dbl_kernel<<<(MROWS * NDP + 255) / 256, 256>>>(dblp, dbl, dbh, dbll);

    // 5) dt = softplus(dbl[:,:64] @ W_dt + b_dt) (3-term)
    mma_gemm<3, 2><<<dim3(DI / 128, MROWS / 128, 1), 256, SMEM3>>>(
        dbh, dbll, Wdh, Wdl, dtb, DTR, DTR, DI, DI, 0, b_dt);

    // 6) selective scan -> y (fp16 hi/lo)
    scan_kernel<<<(BC * DI * 8) / 256, 256>>>(dtb, xc, dbl, xz, A_log, D_par, yh, yl);

    // 7) out = y @ W_out (2-term), K-split 2 -> slabs
    mma_gemm<2, 3><<<dim3(DM / 128, MROWS / 128, 2), 256, SMEM2>>>(
        yh, yl, Woh, nullptr, osp, DI / 2, DI, DM, DM,
        (size_t)MROWS * DM, nullptr);

    // 8) out = slab0 + slab1
    reduce_out_kernel<<<(MROWS * DM / 4 + 255) / 256, 256>>>(
        (const float4*)osp, (const float4*)(osp + (size_t)MROWS * DM),
        (float4*)out, MROWS * DM / 4);
}